// round 5
// baseline (speedup 1.0000x reference)
#include <cuda_runtime.h>
#include <cstdint>

// Problem constants
#define BB 4
#define TT 2048
#define DD 1024
#define HH 16
#define HDIM 64
#define MROWS (BB * TT)            // 8192
#define QKV_N (3 * DD)             // 3072

// Scratch (allocation-free rule: __device__ globals)
__device__ float g_qkv[(size_t)MROWS * QKV_N];   // 96 MB
__device__ float g_att[(size_t)MROWS * DD];      // 32 MB

__device__ __forceinline__ uint32_t f2tf32(float x) {
    uint32_t u;
    asm("cvt.rna.tf32.f32 %0, %1;" : "=r"(u) : "f"(x));
    return u;
}

__device__ __forceinline__ void mma_tf32(float c[4], const uint32_t a[4],
                                         uint32_t b0, uint32_t b1) {
    asm volatile(
        "mma.sync.aligned.m16n8k8.row.col.f32.tf32.tf32.f32 "
        "{%0,%1,%2,%3}, {%4,%5,%6,%7}, {%8,%9}, {%0,%1,%2,%3};"
        : "+f"(c[0]), "+f"(c[1]), "+f"(c[2]), "+f"(c[3])
        : "r"(a[0]), "r"(a[1]), "r"(a[2]), "r"(a[3]), "r"(b0), "r"(b1));
}

__device__ __forceinline__ void cp16(void* dst, const void* src) {
    uint32_t d = (uint32_t)__cvta_generic_to_shared(dst);
    asm volatile("cp.async.cg.shared.global [%0], [%1], 16;" :: "r"(d), "l"(src));
}
__device__ __forceinline__ void cp_commit() {
    asm volatile("cp.async.commit_group;");
}
template <int N> __device__ __forceinline__ void cp_wait() {
    asm volatile("cp.async.wait_group %0;" :: "n"(N));
}

// ---------------------------------------------------------------------------
// TF32 GEMM + bias, 3-stage cp.async pipeline.
// 128x128x32 tile, 256 threads, warp = 64Mx32N. Raw fp32 in SMEM,
// tf32 conversion at fragment load. Dynamic SMEM = 104448 B.
// ---------------------------------------------------------------------------
__global__ __launch_bounds__(256, 2) void gemm_tf32_kernel(
    const float* __restrict__ A, const float* __restrict__ Bm,
    const float* __restrict__ bias, float* __restrict__ C,
    int M, int N, int K)
{
    constexpr int BM = 128, BN = 128, BK = 32, AP = 36;
    constexpr int AW = BM * AP;   // 4608 words per A stage
    constexpr int BW = BK * BN;   // 4096 words per B stage
    extern __shared__ float smf[];
    float* Ab = smf;              // 3 stages
    float* Bb = smf + 3 * AW;     // 3 stages

    const int tid  = threadIdx.x;
    const int lane = tid & 31;
    const int warp = tid >> 5;
    const int bm = blockIdx.y * BM;
    const int bn = blockIdx.x * BN;
    const int wm = (warp & 1) * 64;
    const int wn = (warp >> 1) * 32;
    const int gr = lane >> 2;
    const int gc = lane & 3;

    const int ar0 = tid >> 3;                 // A row for i=0 (stride 32 rows)
    const int ac4 = (tid & 7) * 4;            // A col
    const int bk0 = tid >> 5;                 // B k-row for i=0 (stride 8)
    const int bc4 = (tid & 31) * 4;           // B col (pre-swizzle)

    auto prefetch = [&](int it, int s) {
        const int k0 = it * BK;
        float* Ad = Ab + s * AW;
        float* Bd = Bb + s * BW;
#pragma unroll
        for (int i = 0; i < 4; i++) {
            int r = ar0 + i * 32;
            cp16(Ad + r * AP + ac4, A + (size_t)(bm + r) * K + k0 + ac4);
        }
#pragma unroll
        for (int i = 0; i < 4; i++) {
            int kr = bk0 + i * 8;
            cp16(Bd + kr * BN + (bc4 ^ ((kr & 3) * 8)),
                 Bm + (size_t)(k0 + kr) * N + bn + bc4);
        }
    };

    float c[4][4][4];
#pragma unroll
    for (int i = 0; i < 4; i++)
#pragma unroll
        for (int j = 0; j < 4; j++)
#pragma unroll
            for (int r = 0; r < 4; r++) c[i][j][r] = 0.0f;

    const int nit = K / BK;       // 32
    prefetch(0, 0); cp_commit();
    prefetch(1, 1); cp_commit();

    for (int it = 0; it < nit; it++) {
        if (it + 2 < nit) { prefetch(it + 2, (it + 2) % 3); cp_commit(); cp_wait<2>(); }
        else if (it + 1 < nit) cp_wait<1>();
        else cp_wait<0>();
        __syncthreads();

        const float* Af = Ab + (it % 3) * AW;
        const float* Bf = Bb + (it % 3) * BW;

#pragma unroll
        for (int ks = 0; ks < 4; ks++) {
            const int kb = ks * 8;
            uint32_t a[4][4];
#pragma unroll
            for (int i = 0; i < 4; i++) {
                const float* ar = &Af[(wm + i * 16 + gr) * AP + kb + gc];
                a[i][0] = f2tf32(ar[0]);
                a[i][1] = f2tf32(ar[8 * AP]);
                a[i][2] = f2tf32(ar[4]);
                a[i][3] = f2tf32(ar[8 * AP + 4]);
            }
            uint32_t b[4][2];
#pragma unroll
            for (int j = 0; j < 4; j++) {
                int n  = wn + j * 8 + gr;
                int k1 = kb + gc;
                int k2 = kb + gc + 4;
                b[j][0] = f2tf32(Bf[k1 * BN + (n ^ ((k1 & 3) * 8))]);
                b[j][1] = f2tf32(Bf[k2 * BN + (n ^ ((k2 & 3) * 8))]);
            }
#pragma unroll
            for (int i = 0; i < 4; i++)
#pragma unroll
                for (int j = 0; j < 4; j++)
                    mma_tf32(c[i][j], a[i], b[j][0], b[j][1]);
        }
        __syncthreads();
    }

#pragma unroll
    for (int i = 0; i < 4; i++) {
#pragma unroll
        for (int j = 0; j < 4; j++) {
            int row = bm + wm + i * 16 + gr;
            int col = bn + wn + j * 8 + 2 * gc;
            float bx = bias[col], by = bias[col + 1];
            float2 o0 = make_float2(c[i][j][0] + bx, c[i][j][1] + by);
            float2 o1 = make_float2(c[i][j][2] + bx, c[i][j][3] + by);
            *(float2*)(C + (size_t)row * N + col)       = o0;
            *(float2*)(C + (size_t)(row + 8) * N + col) = o1;
        }
    }
}

// ---------------------------------------------------------------------------
// Tensor-core causal flash attention, 128-query tiles, cp.async double buffer.
// 128 threads / 4 warps; each warp owns 32 query rows (two 16-row chunks).
// SMEM: QP[128][68] (Q then P, tf32) + 2x K[64][68] + 2x V[64][64] raw fp32.
// Dynamic SMEM = 102400 B; 2 blocks/SM.
// ---------------------------------------------------------------------------
__global__ __launch_bounds__(128, 2) void attn_tc_kernel(
    const float* __restrict__ qkv, float* __restrict__ out)
{
    constexpr int QP = 68;
    extern __shared__ float smf[];
    uint32_t* QPs = (uint32_t*)smf;                 // [128][68]
    float* Kb0 = smf + 128 * QP;                    // [64][68]
    float* Kb1 = Kb0 + 64 * QP;
    float* Vb0 = Kb1 + 64 * QP;                     // [64][64] xor-swizzled
    float* Vb1 = Vb0 + 64 * 64;

    const int tid  = threadIdx.x;
    const int lane = tid & 31;
    const int w    = tid >> 5;
    const int gr   = lane >> 2;
    const int gc   = lane & 3;
    const int qt = blockIdx.x;
    const int h  = blockIdx.y;
    const int b  = blockIdx.z;
    const size_t rs = QKV_N;
    const int qbase_g = qt * 128;

    auto prefetch = [&](int kt, int pb) {
        const float* kg = qkv + ((size_t)(b * TT + kt * 64)) * rs + DD + h * HDIM;
        const float* vg = kg + DD;
        float* Kd = pb ? Kb1 : Kb0;
        float* Vd = pb ? Vb1 : Vb0;
#pragma unroll
        for (int it = 0; it < 8; it++) {
            int idx = it * 128 + tid;
            int row = idx >> 4;
            int c4  = (idx & 15) * 4;
            cp16(Kd + row * QP + c4, kg + (size_t)row * rs + c4);
            cp16(Vd + row * 64 + (c4 ^ ((row & 3) * 8)), vg + (size_t)row * rs + c4);
        }
    };

    prefetch(0, 0); cp_commit();

    // ---- stage Q tile (128 rows, scaled by 1/8, tf32) ----
    const float* qg = qkv + ((size_t)(b * TT + qbase_g)) * rs + h * HDIM;
#pragma unroll
    for (int it = 0; it < 16; it++) {
        int idx = it * 128 + tid;
        int row = idx >> 4;
        int c4  = (idx & 15) * 4;
        float4 v = *(const float4*)(qg + (size_t)row * rs + c4);
        uint4 t;
        t.x = f2tf32(v.x * 0.125f); t.y = f2tf32(v.y * 0.125f);
        t.z = f2tf32(v.z * 0.125f); t.w = f2tf32(v.w * 0.125f);
        *(uint4*)&QPs[row * QP + c4] = t;
    }
    __syncthreads();

    // ---- Q fragments: 2 chunks of 16 rows per warp ----
    uint32_t qf[2][8][4];
#pragma unroll
    for (int mi = 0; mi < 2; mi++) {
        const uint32_t* qb = &QPs[(w * 32 + mi * 16 + gr) * QP + gc];
#pragma unroll
        for (int ks = 0; ks < 8; ks++) {
            qf[mi][ks][0] = qb[ks * 8];
            qf[mi][ks][1] = qb[8 * QP + ks * 8];
            qf[mi][ks][2] = qb[ks * 8 + 4];
            qf[mi][ks][3] = qb[8 * QP + ks * 8 + 4];
        }
    }

    float o[2][8][4];
#pragma unroll
    for (int mi = 0; mi < 2; mi++)
#pragma unroll
        for (int j = 0; j < 8; j++)
#pragma unroll
            for (int r = 0; r < 4; r++) o[mi][j][r] = 0.0f;
    float mS[2][2] = {{-1e30f, -1e30f}, {-1e30f, -1e30f}};
    float lS[2][2] = {{0.0f, 0.0f}, {0.0f, 0.0f}};

    const int ntiles = 2 * qt + 2;
    for (int kt = 0; kt < ntiles; kt++) {
        if (kt + 1 < ntiles) { prefetch(kt + 1, (kt + 1) & 1); cp_commit(); cp_wait<1>(); }
        else cp_wait<0>();
        __syncthreads();
        const float* Kf = (kt & 1) ? Kb1 : Kb0;
        const float* Vf = (kt & 1) ? Vb1 : Vb0;

#pragma unroll
        for (int mi = 0; mi < 2; mi++) {
            const int wbase_g = qbase_g + w * 32 + mi * 16;
            if (kt * 64 > wbase_g) continue;   // chunk fully masked: skip

            // ---- S = Q @ K^T ----
            float s[8][4];
#pragma unroll
            for (int j = 0; j < 8; j++) {
                s[j][0] = s[j][1] = s[j][2] = s[j][3] = 0.0f;
                const float* kb2 = &Kf[(j * 8 + gr) * QP + gc];
#pragma unroll
                for (int ks = 0; ks < 8; ks++) {
                    uint32_t b0 = f2tf32(kb2[ks * 8]);
                    uint32_t b1 = f2tf32(kb2[ks * 8 + 4]);
                    mma_tf32(s[j], qf[mi][ks], b0, b1);
                }
            }

            // ---- causal mask (boundary tiles only) ----
            if (kt * 64 + 63 > wbase_g) {
                const int row0 = wbase_g + gr;
                const int row1 = row0 + 8;
#pragma unroll
                for (int j = 0; j < 8; j++) {
                    int key0 = kt * 64 + j * 8 + 2 * gc;
                    if (key0     > row0) s[j][0] = -1e30f;
                    if (key0 + 1 > row0) s[j][1] = -1e30f;
                    if (key0     > row1) s[j][2] = -1e30f;
                    if (key0 + 1 > row1) s[j][3] = -1e30f;
                }
            }

            // ---- online softmax (register row-state, quad shfl reduce) ----
            float mx0 = -1e30f, mx1 = -1e30f;
#pragma unroll
            for (int j = 0; j < 8; j++) {
                mx0 = fmaxf(mx0, fmaxf(s[j][0], s[j][1]));
                mx1 = fmaxf(mx1, fmaxf(s[j][2], s[j][3]));
            }
            mx0 = fmaxf(mx0, __shfl_xor_sync(0xffffffffu, mx0, 1));
            mx0 = fmaxf(mx0, __shfl_xor_sync(0xffffffffu, mx0, 2));
            mx1 = fmaxf(mx1, __shfl_xor_sync(0xffffffffu, mx1, 1));
            mx1 = fmaxf(mx1, __shfl_xor_sync(0xffffffffu, mx1, 2));

            float mn0 = fmaxf(mS[mi][0], mx0), mn1 = fmaxf(mS[mi][1], mx1);
            float cr0 = __expf(mS[mi][0] - mn0), cr1 = __expf(mS[mi][1] - mn1);
            lS[mi][0] *= cr0; lS[mi][1] *= cr1;
#pragma unroll
            for (int j = 0; j < 8; j++) {
                o[mi][j][0] *= cr0; o[mi][j][1] *= cr0;
                o[mi][j][2] *= cr1; o[mi][j][3] *= cr1;
            }

            float rs0 = 0.0f, rs1 = 0.0f;
            uint32_t* prow = &QPs[(w * 32 + mi * 16 + gr) * QP + 2 * gc];
#pragma unroll
            for (int j = 0; j < 8; j++) {
                float p0 = __expf(s[j][0] - mn0);
                float p1 = __expf(s[j][1] - mn0);
                float p2 = __expf(s[j][2] - mn1);
                float p3 = __expf(s[j][3] - mn1);
                rs0 += p0 + p1; rs1 += p2 + p3;
                *(uint2*)&prow[j * 8]          = make_uint2(f2tf32(p0), f2tf32(p1));
                *(uint2*)&prow[8 * QP + j * 8] = make_uint2(f2tf32(p2), f2tf32(p3));
            }
            rs0 += __shfl_xor_sync(0xffffffffu, rs0, 1);
            rs0 += __shfl_xor_sync(0xffffffffu, rs0, 2);
            rs1 += __shfl_xor_sync(0xffffffffu, rs1, 1);
            rs1 += __shfl_xor_sync(0xffffffffu, rs1, 2);
            lS[mi][0] += rs0; lS[mi][1] += rs1;
            mS[mi][0] = mn0; mS[mi][1] = mn1;
            __syncwarp();   // P rows warp-private

            // ---- P fragments ----
            uint32_t pf[8][4];
            {
                const uint32_t* pb = &QPs[(w * 32 + mi * 16 + gr) * QP + gc];
#pragma unroll
                for (int kc = 0; kc < 8; kc++) {
                    pf[kc][0] = pb[kc * 8];
                    pf[kc][1] = pb[8 * QP + kc * 8];
                    pf[kc][2] = pb[kc * 8 + 4];
                    pf[kc][3] = pb[8 * QP + kc * 8 + 4];
                }
            }

            // ---- O += P @ V ----
#pragma unroll
            for (int j = 0; j < 8; j++) {
                const int csw = (j * 8 + gr) ^ (gc * 8);
#pragma unroll
                for (int kc = 0; kc < 8; kc++) {
                    uint32_t b0 = f2tf32(Vf[(kc * 8 + gc) * 64 + csw]);
                    uint32_t b1 = f2tf32(Vf[(kc * 8 + gc + 4) * 64 + csw]);
                    mma_tf32(o[mi][j], pf[kc], b0, b1);
                }
            }
        }
        __syncthreads();   // all warps done with Kf/Vf before overwrite
    }

    // ---- epilogue ----
#pragma unroll
    for (int mi = 0; mi < 2; mi++) {
        float iv0 = 1.0f / lS[mi][0], iv1 = 1.0f / lS[mi][1];
        int q0 = qbase_g + w * 32 + mi * 16 + gr;
        float* out0 = out + ((size_t)(b * TT + q0)) * DD + h * HDIM + 2 * gc;
        float* out1 = out0 + (size_t)8 * DD;
#pragma unroll
        for (int j = 0; j < 8; j++) {
            *(float2*)(out0 + j * 8) = make_float2(o[mi][j][0] * iv0, o[mi][j][1] * iv0);
            *(float2*)(out1 + j * 8) = make_float2(o[mi][j][2] * iv1, o[mi][j][3] * iv1);
        }
    }
}

// ---------------------------------------------------------------------------
// Launch
// ---------------------------------------------------------------------------
extern "C" void kernel_launch(void* const* d_in, const int* in_sizes, int n_in,
                              void* d_out, int out_size)
{
    const float* x      = (const float*)d_in[0];
    const float* qkv_w  = (const float*)d_in[1];
    const float* qkv_b  = (const float*)d_in[2];
    const float* proj_w = (const float*)d_in[3];
    const float* proj_b = (const float*)d_in[4];
    float* out = (float*)d_out;

    float *qkv_s, *att_s;
    cudaGetSymbolAddress((void**)&qkv_s, g_qkv);
    cudaGetSymbolAddress((void**)&att_s, g_att);

    const int GEMM_SMEM = 3 * (128 * 36 + 32 * 128) * sizeof(float);   // 104448
    const int ATTN_SMEM = (128 * 68 + 2 * 64 * 68 + 2 * 64 * 64) * sizeof(float); // 102400
    cudaFuncSetAttribute(gemm_tf32_kernel,
                         cudaFuncAttributeMaxDynamicSharedMemorySize, GEMM_SMEM);
    cudaFuncSetAttribute(attn_tc_kernel,
                         cudaFuncAttributeMaxDynamicSharedMemorySize, ATTN_SMEM);

    // 1) QKV GEMM: [8192,1024] @ [1024,3072] + bias
    dim3 g1(QKV_N / 128, MROWS / 128);
    gemm_tf32_kernel<<<g1, 256, GEMM_SMEM>>>(x, qkv_w, qkv_b, qkv_s, MROWS, QKV_N, DD);

    // 2) Causal multi-head attention (tensor cores, 128-query tiles)
    dim3 ga(TT / 128, HH, BB);
    attn_tc_kernel<<<ga, 128, ATTN_SMEM>>>(qkv_s, att_s);

    // 3) Output projection: [8192,1024] @ [1024,1024] + bias
    dim3 g2(DD / 128, MROWS / 128);
    gemm_tf32_kernel<<<g2, 256, GEMM_SMEM>>>(att_s, proj_w, proj_b, out, MROWS, DD, DD);
}

// round 6
// speedup vs baseline: 1.1472x; 1.1472x over previous
#include <cuda_runtime.h>
#include <cstdint>

// Problem constants
#define BB 4
#define TT 2048
#define DD 1024
#define HH 16
#define HDIM 64
#define MROWS (BB * TT)            // 8192
#define QKV_N (3 * DD)             // 3072

// Scratch (allocation-free rule: __device__ globals)
__device__ float g_qkv[(size_t)MROWS * QKV_N];   // 96 MB  (pre-truncated tf32 bits)
__device__ float g_att[(size_t)MROWS * DD];      // 32 MB  (pre-truncated tf32 bits)
__device__ float g_xt[(size_t)MROWS * DD];       // 32 MB  truncated x
__device__ float g_wqkv[(size_t)DD * QKV_N];     // 12 MB  truncated qkv_w
__device__ float g_wproj[(size_t)DD * DD];       //  4 MB  truncated proj_w

__device__ __forceinline__ uint32_t f2tf32(float x) {
    uint32_t u;
    asm("cvt.rna.tf32.f32 %0, %1;" : "=r"(u) : "f"(x));
    return u;
}

__device__ __forceinline__ void mma_tf32(float c[4], const uint32_t a[4],
                                         uint32_t b0, uint32_t b1) {
    asm volatile(
        "mma.sync.aligned.m16n8k8.row.col.f32.tf32.tf32.f32 "
        "{%0,%1,%2,%3}, {%4,%5,%6,%7}, {%8,%9}, {%0,%1,%2,%3};"
        : "+f"(c[0]), "+f"(c[1]), "+f"(c[2]), "+f"(c[3])
        : "r"(a[0]), "r"(a[1]), "r"(a[2]), "r"(a[3]), "r"(b0), "r"(b1));
}

__device__ __forceinline__ void cp16(void* dst, const void* src) {
    uint32_t d = (uint32_t)__cvta_generic_to_shared(dst);
    asm volatile("cp.async.cg.shared.global [%0], [%1], 16;" :: "r"(d), "l"(src));
}
__device__ __forceinline__ void cp_commit() {
    asm volatile("cp.async.commit_group;");
}
template <int N> __device__ __forceinline__ void cp_wait() {
    asm volatile("cp.async.wait_group %0;" :: "n"(N));
}

// ---------------------------------------------------------------------------
// Truncate fp32 -> tf32 bit pattern (round-to-nearest), elementwise.
// ---------------------------------------------------------------------------
__global__ __launch_bounds__(256) void trunc_kernel(
    const float4* __restrict__ src, float4* __restrict__ dst, int n4)
{
    int i = blockIdx.x * blockDim.x + threadIdx.x;
    int stride = gridDim.x * blockDim.x;
    for (; i < n4; i += stride) {
        float4 v = src[i];
        v.x = __uint_as_float(f2tf32(v.x));
        v.y = __uint_as_float(f2tf32(v.y));
        v.z = __uint_as_float(f2tf32(v.z));
        v.w = __uint_as_float(f2tf32(v.w));
        dst[i] = v;
    }
}

// ---------------------------------------------------------------------------
// TF32 GEMM + bias, 3-stage cp.async pipeline, inputs pre-truncated.
// 128x128x32 tile, 256 threads, warp = 64Mx32N. No cvt in mainloop.
// TRUNC_OUT: epilogue rounds output to tf32 bits (for attention consumers).
// ---------------------------------------------------------------------------
template <bool TRUNC_OUT>
__global__ __launch_bounds__(256, 2) void gemm_tf32_kernel(
    const float* __restrict__ A, const float* __restrict__ Bm,
    const float* __restrict__ bias, float* __restrict__ C,
    int M, int N, int K)
{
    constexpr int BM = 128, BN = 128, BK = 32, AP = 36;
    constexpr int AW = BM * AP;
    constexpr int BW = BK * BN;
    extern __shared__ float smf[];
    float* Ab = smf;
    float* Bb = smf + 3 * AW;

    const int tid  = threadIdx.x;
    const int lane = tid & 31;
    const int warp = tid >> 5;
    const int bm = blockIdx.y * BM;
    const int bn = blockIdx.x * BN;
    const int wm = (warp & 1) * 64;
    const int wn = (warp >> 1) * 32;
    const int gr = lane >> 2;
    const int gc = lane & 3;

    const int ar0 = tid >> 3;
    const int ac4 = (tid & 7) * 4;
    const int bk0 = tid >> 5;
    const int bc4 = (tid & 31) * 4;

    auto prefetch = [&](int it, int s) {
        const int k0 = it * BK;
        float* Ad = Ab + s * AW;
        float* Bd = Bb + s * BW;
#pragma unroll
        for (int i = 0; i < 4; i++) {
            int r = ar0 + i * 32;
            cp16(Ad + r * AP + ac4, A + (size_t)(bm + r) * K + k0 + ac4);
        }
#pragma unroll
        for (int i = 0; i < 4; i++) {
            int kr = bk0 + i * 8;
            cp16(Bd + kr * BN + (bc4 ^ ((kr & 3) * 8)),
                 Bm + (size_t)(k0 + kr) * N + bn + bc4);
        }
    };

    float c[4][4][4];
#pragma unroll
    for (int i = 0; i < 4; i++)
#pragma unroll
        for (int j = 0; j < 4; j++)
#pragma unroll
            for (int r = 0; r < 4; r++) c[i][j][r] = 0.0f;

    const int nit = K / BK;
    prefetch(0, 0); cp_commit();
    prefetch(1, 1); cp_commit();

    for (int it = 0; it < nit; it++) {
        if (it + 2 < nit) { prefetch(it + 2, (it + 2) % 3); cp_commit(); cp_wait<2>(); }
        else if (it + 1 < nit) cp_wait<1>();
        else cp_wait<0>();
        __syncthreads();

        const uint32_t* Af = (const uint32_t*)(Ab + (it % 3) * AW);
        const uint32_t* Bf = (const uint32_t*)(Bb + (it % 3) * BW);

#pragma unroll
        for (int ks = 0; ks < 4; ks++) {
            const int kb = ks * 8;
            uint32_t a[4][4];
#pragma unroll
            for (int i = 0; i < 4; i++) {
                const uint32_t* ar = &Af[(wm + i * 16 + gr) * AP + kb + gc];
                a[i][0] = ar[0];
                a[i][1] = ar[8 * AP];
                a[i][2] = ar[4];
                a[i][3] = ar[8 * AP + 4];
            }
            uint32_t b[4][2];
#pragma unroll
            for (int j = 0; j < 4; j++) {
                int n  = wn + j * 8 + gr;
                int k1 = kb + gc;
                int k2 = kb + gc + 4;
                b[j][0] = Bf[k1 * BN + (n ^ ((k1 & 3) * 8))];
                b[j][1] = Bf[k2 * BN + (n ^ ((k2 & 3) * 8))];
            }
#pragma unroll
            for (int i = 0; i < 4; i++)
#pragma unroll
                for (int j = 0; j < 4; j++)
                    mma_tf32(c[i][j], a[i], b[j][0], b[j][1]);
        }
        __syncthreads();
    }

#pragma unroll
    for (int i = 0; i < 4; i++) {
#pragma unroll
        for (int j = 0; j < 4; j++) {
            int row = bm + wm + i * 16 + gr;
            int col = bn + wn + j * 8 + 2 * gc;
            float bx = bias[col], by = bias[col + 1];
            float v0 = c[i][j][0] + bx, v1 = c[i][j][1] + by;
            float v2 = c[i][j][2] + bx, v3 = c[i][j][3] + by;
            if (TRUNC_OUT) {
                v0 = __uint_as_float(f2tf32(v0));
                v1 = __uint_as_float(f2tf32(v1));
                v2 = __uint_as_float(f2tf32(v2));
                v3 = __uint_as_float(f2tf32(v3));
            }
            *(float2*)(C + (size_t)row * N + col)       = make_float2(v0, v1);
            *(float2*)(C + (size_t)(row + 8) * N + col) = make_float2(v2, v3);
        }
    }
}

// ---------------------------------------------------------------------------
// Tensor-core causal flash attention, 128-query tiles, cp.async double buffer.
// Inputs pre-truncated tf32 bits -> no cvt in the mma loops.
// SMEM: QP[128][68] + 2x K[64][68] + 2x V[64][64] = 102400 B.
// ---------------------------------------------------------------------------
__global__ __launch_bounds__(128, 2) void attn_tc_kernel(
    const float* __restrict__ qkv, float* __restrict__ out)
{
    constexpr int QP = 68;
    extern __shared__ float smf[];
    uint32_t* QPs = (uint32_t*)smf;                 // [128][68]
    float* Kb0 = smf + 128 * QP;
    float* Kb1 = Kb0 + 64 * QP;
    float* Vb0 = Kb1 + 64 * QP;
    float* Vb1 = Vb0 + 64 * 64;

    const int tid  = threadIdx.x;
    const int lane = tid & 31;
    const int w    = tid >> 5;
    const int gr   = lane >> 2;
    const int gc   = lane & 3;
    const int qt = blockIdx.x;
    const int h  = blockIdx.y;
    const int b  = blockIdx.z;
    const size_t rs = QKV_N;
    const int qbase_g = qt * 128;

    auto prefetch = [&](int kt, int pb) {
        const float* kg = qkv + ((size_t)(b * TT + kt * 64)) * rs + DD + h * HDIM;
        const float* vg = kg + DD;
        float* Kd = pb ? Kb1 : Kb0;
        float* Vd = pb ? Vb1 : Vb0;
#pragma unroll
        for (int it = 0; it < 8; it++) {
            int idx = it * 128 + tid;
            int row = idx >> 4;
            int c4  = (idx & 15) * 4;
            cp16(Kd + row * QP + c4, kg + (size_t)row * rs + c4);
            cp16(Vd + row * 64 + (c4 ^ ((row & 3) * 8)), vg + (size_t)row * rs + c4);
        }
    };

    prefetch(0, 0); cp_commit();

    // ---- stage Q tile (scale by 1/8 = power of two: stays valid tf32) ----
    const float* qg = qkv + ((size_t)(b * TT + qbase_g)) * rs + h * HDIM;
#pragma unroll
    for (int it = 0; it < 16; it++) {
        int idx = it * 128 + tid;
        int row = idx >> 4;
        int c4  = (idx & 15) * 4;
        float4 v = *(const float4*)(qg + (size_t)row * rs + c4);
        v.x *= 0.125f; v.y *= 0.125f; v.z *= 0.125f; v.w *= 0.125f;
        *(float4*)&QPs[row * QP + c4] = v;
    }
    __syncthreads();

    // ---- Q fragments: 2 chunks of 16 rows per warp ----
    uint32_t qf[2][8][4];
#pragma unroll
    for (int mi = 0; mi < 2; mi++) {
        const uint32_t* qb = &QPs[(w * 32 + mi * 16 + gr) * QP + gc];
#pragma unroll
        for (int ks = 0; ks < 8; ks++) {
            qf[mi][ks][0] = qb[ks * 8];
            qf[mi][ks][1] = qb[8 * QP + ks * 8];
            qf[mi][ks][2] = qb[ks * 8 + 4];
            qf[mi][ks][3] = qb[8 * QP + ks * 8 + 4];
        }
    }

    float o[2][8][4];
#pragma unroll
    for (int mi = 0; mi < 2; mi++)
#pragma unroll
        for (int j = 0; j < 8; j++)
#pragma unroll
            for (int r = 0; r < 4; r++) o[mi][j][r] = 0.0f;
    float mS[2][2] = {{-1e30f, -1e30f}, {-1e30f, -1e30f}};
    float lS[2][2] = {{0.0f, 0.0f}, {0.0f, 0.0f}};

    const int ntiles = 2 * qt + 2;
    for (int kt = 0; kt < ntiles; kt++) {
        if (kt + 1 < ntiles) { prefetch(kt + 1, (kt + 1) & 1); cp_commit(); cp_wait<1>(); }
        else cp_wait<0>();
        __syncthreads();
        const uint32_t* Kf = (const uint32_t*)((kt & 1) ? Kb1 : Kb0);
        const uint32_t* Vf = (const uint32_t*)((kt & 1) ? Vb1 : Vb0);

#pragma unroll
        for (int mi = 0; mi < 2; mi++) {
            const int wbase_g = qbase_g + w * 32 + mi * 16;
            if (kt * 64 > wbase_g) continue;   // chunk fully masked: skip

            // ---- S = Q @ K^T ----
            float s[8][4];
#pragma unroll
            for (int j = 0; j < 8; j++) {
                s[j][0] = s[j][1] = s[j][2] = s[j][3] = 0.0f;
                const uint32_t* kb2 = &Kf[(j * 8 + gr) * QP + gc];
#pragma unroll
                for (int ks = 0; ks < 8; ks++)
                    mma_tf32(s[j], qf[mi][ks], kb2[ks * 8], kb2[ks * 8 + 4]);
            }

            // ---- causal mask (boundary tiles only) ----
            if (kt * 64 + 63 > wbase_g) {
                const int row0 = wbase_g + gr;
                const int row1 = row0 + 8;
#pragma unroll
                for (int j = 0; j < 8; j++) {
                    int key0 = kt * 64 + j * 8 + 2 * gc;
                    if (key0     > row0) s[j][0] = -1e30f;
                    if (key0 + 1 > row0) s[j][1] = -1e30f;
                    if (key0     > row1) s[j][2] = -1e30f;
                    if (key0 + 1 > row1) s[j][3] = -1e30f;
                }
            }

            // ---- online softmax ----
            float mx0 = -1e30f, mx1 = -1e30f;
#pragma unroll
            for (int j = 0; j < 8; j++) {
                mx0 = fmaxf(mx0, fmaxf(s[j][0], s[j][1]));
                mx1 = fmaxf(mx1, fmaxf(s[j][2], s[j][3]));
            }
            mx0 = fmaxf(mx0, __shfl_xor_sync(0xffffffffu, mx0, 1));
            mx0 = fmaxf(mx0, __shfl_xor_sync(0xffffffffu, mx0, 2));
            mx1 = fmaxf(mx1, __shfl_xor_sync(0xffffffffu, mx1, 1));
            mx1 = fmaxf(mx1, __shfl_xor_sync(0xffffffffu, mx1, 2));

            float mn0 = fmaxf(mS[mi][0], mx0), mn1 = fmaxf(mS[mi][1], mx1);
            float cr0 = __expf(mS[mi][0] - mn0), cr1 = __expf(mS[mi][1] - mn1);
            lS[mi][0] *= cr0; lS[mi][1] *= cr1;
#pragma unroll
            for (int j = 0; j < 8; j++) {
                o[mi][j][0] *= cr0; o[mi][j][1] *= cr0;
                o[mi][j][2] *= cr1; o[mi][j][3] *= cr1;
            }

            float rs0 = 0.0f, rs1 = 0.0f;
            uint32_t* prow = &QPs[(w * 32 + mi * 16 + gr) * QP + 2 * gc];
#pragma unroll
            for (int j = 0; j < 8; j++) {
                float p0 = __expf(s[j][0] - mn0);
                float p1 = __expf(s[j][1] - mn0);
                float p2 = __expf(s[j][2] - mn1);
                float p3 = __expf(s[j][3] - mn1);
                rs0 += p0 + p1; rs1 += p2 + p3;
                *(uint2*)&prow[j * 8]          = make_uint2(f2tf32(p0), f2tf32(p1));
                *(uint2*)&prow[8 * QP + j * 8] = make_uint2(f2tf32(p2), f2tf32(p3));
            }
            rs0 += __shfl_xor_sync(0xffffffffu, rs0, 1);
            rs0 += __shfl_xor_sync(0xffffffffu, rs0, 2);
            rs1 += __shfl_xor_sync(0xffffffffu, rs1, 1);
            rs1 += __shfl_xor_sync(0xffffffffu, rs1, 2);
            lS[mi][0] += rs0; lS[mi][1] += rs1;
            mS[mi][0] = mn0; mS[mi][1] = mn1;
            __syncwarp();   // P rows warp-private

            // ---- P fragments ----
            uint32_t pf[8][4];
            {
                const uint32_t* pb = &QPs[(w * 32 + mi * 16 + gr) * QP + gc];
#pragma unroll
                for (int kc = 0; kc < 8; kc++) {
                    pf[kc][0] = pb[kc * 8];
                    pf[kc][1] = pb[8 * QP + kc * 8];
                    pf[kc][2] = pb[kc * 8 + 4];
                    pf[kc][3] = pb[8 * QP + kc * 8 + 4];
                }
            }

            // ---- O += P @ V ----
#pragma unroll
            for (int j = 0; j < 8; j++) {
                const int csw = (j * 8 + gr) ^ (gc * 8);
#pragma unroll
                for (int kc = 0; kc < 8; kc++)
                    mma_tf32(o[mi][j], pf[kc],
                             Vf[(kc * 8 + gc) * 64 + csw],
                             Vf[(kc * 8 + gc + 4) * 64 + csw]);
            }
        }
        __syncthreads();
    }

    // ---- epilogue: normalize, truncate to tf32 bits (proj input) ----
#pragma unroll
    for (int mi = 0; mi < 2; mi++) {
        float iv0 = 1.0f / lS[mi][0], iv1 = 1.0f / lS[mi][1];
        int q0 = qbase_g + w * 32 + mi * 16 + gr;
        float* out0 = out + ((size_t)(b * TT + q0)) * DD + h * HDIM + 2 * gc;
        float* out1 = out0 + (size_t)8 * DD;
#pragma unroll
        for (int j = 0; j < 8; j++) {
            float a0 = __uint_as_float(f2tf32(o[mi][j][0] * iv0));
            float a1 = __uint_as_float(f2tf32(o[mi][j][1] * iv0));
            float a2 = __uint_as_float(f2tf32(o[mi][j][2] * iv1));
            float a3 = __uint_as_float(f2tf32(o[mi][j][3] * iv1));
            *(float2*)(out0 + j * 8) = make_float2(a0, a1);
            *(float2*)(out1 + j * 8) = make_float2(a2, a3);
        }
    }
}

// ---------------------------------------------------------------------------
// Launch
// ---------------------------------------------------------------------------
extern "C" void kernel_launch(void* const* d_in, const int* in_sizes, int n_in,
                              void* d_out, int out_size)
{
    const float* x      = (const float*)d_in[0];
    const float* qkv_w  = (const float*)d_in[1];
    const float* qkv_b  = (const float*)d_in[2];
    const float* proj_w = (const float*)d_in[3];
    const float* proj_b = (const float*)d_in[4];
    float* out = (float*)d_out;

    float *qkv_s, *att_s, *xt, *wqkv, *wproj;
    cudaGetSymbolAddress((void**)&qkv_s, g_qkv);
    cudaGetSymbolAddress((void**)&att_s, g_att);
    cudaGetSymbolAddress((void**)&xt,    g_xt);
    cudaGetSymbolAddress((void**)&wqkv,  g_wqkv);
    cudaGetSymbolAddress((void**)&wproj, g_wproj);

    const int GEMM_SMEM = 3 * (128 * 36 + 32 * 128) * sizeof(float);   // 104448
    const int ATTN_SMEM = (128 * 68 + 2 * 64 * 68 + 2 * 64 * 64) * sizeof(float); // 102400
    cudaFuncSetAttribute(gemm_tf32_kernel<true>,
                         cudaFuncAttributeMaxDynamicSharedMemorySize, GEMM_SMEM);
    cudaFuncSetAttribute(gemm_tf32_kernel<false>,
                         cudaFuncAttributeMaxDynamicSharedMemorySize, GEMM_SMEM);
    cudaFuncSetAttribute(attn_tc_kernel,
                         cudaFuncAttributeMaxDynamicSharedMemorySize, ATTN_SMEM);

    // 0) Pre-truncate inputs to tf32 bit patterns
    trunc_kernel<<<512, 256>>>((const float4*)x,      (float4*)xt,    MROWS * DD / 4);
    trunc_kernel<<<512, 256>>>((const float4*)qkv_w,  (float4*)wqkv,  DD * QKV_N / 4);
    trunc_kernel<<<256, 256>>>((const float4*)proj_w, (float4*)wproj, DD * DD / 4);

    // 1) QKV GEMM (truncated output feeds attention)
    dim3 g1(QKV_N / 128, MROWS / 128);
    gemm_tf32_kernel<true><<<g1, 256, GEMM_SMEM>>>(xt, wqkv, qkv_b, qkv_s,
                                                   MROWS, QKV_N, DD);

    // 2) Causal multi-head attention (tensor cores)
    dim3 ga(TT / 128, HH, BB);
    attn_tc_kernel<<<ga, 128, ATTN_SMEM>>>(qkv_s, att_s);

    // 3) Output projection (full-precision output)
    dim3 g2(DD / 128, MROWS / 128);
    gemm_tf32_kernel<false><<<g2, 256, GEMM_SMEM>>>(att_s, wproj, proj_b, out,
                                                    MROWS, DD, DD);
}

// round 8
// speedup vs baseline: 1.2540x; 1.0931x over previous
#include <cuda_runtime.h>
#include <cstdint>

// Problem constants
#define BB 4
#define TT 2048
#define DD 1024
#define HH 16
#define HDIM 64
#define MROWS (BB * TT)            // 8192
#define QKV_N (3 * DD)             // 3072

// Scratch (allocation-free rule: __device__ globals)
__device__ float g_qkv[(size_t)MROWS * QKV_N];   // 96 MB row-major tf32-truncated QKV
__device__ float g_att[(size_t)MROWS * DD];      // 32 MB PACKED-A attention output
__device__ float g_xt[(size_t)MROWS * DD];       // 32 MB PACKED-A truncated x
__device__ float g_wqkv[(size_t)DD * QKV_N];     // 12 MB PACKED-B truncated qkv_w
__device__ float g_wproj[(size_t)DD * DD];       //  4 MB PACKED-B truncated proj_w

__device__ __forceinline__ uint32_t f2tf32(float x) {
    uint32_t u;
    asm("cvt.rna.tf32.f32 %0, %1;" : "=r"(u) : "f"(x));
    return u;
}
__device__ __forceinline__ float tft(float x) { return __uint_as_float(f2tf32(x)); }

__device__ __forceinline__ void mma_tf32(float c[4], const uint32_t a[4],
                                         uint32_t b0, uint32_t b1) {
    asm volatile(
        "mma.sync.aligned.m16n8k8.row.col.f32.tf32.tf32.f32 "
        "{%0,%1,%2,%3}, {%4,%5,%6,%7}, {%8,%9}, {%0,%1,%2,%3};"
        : "+f"(c[0]), "+f"(c[1]), "+f"(c[2]), "+f"(c[3])
        : "r"(a[0]), "r"(a[1]), "r"(a[2]), "r"(a[3]), "r"(b0), "r"(b1));
}
__device__ __forceinline__ void mma_tf32_v(float c[4], uint4 a, uint2 b) {
    asm volatile(
        "mma.sync.aligned.m16n8k8.row.col.f32.tf32.tf32.f32 "
        "{%0,%1,%2,%3}, {%4,%5,%6,%7}, {%8,%9}, {%0,%1,%2,%3};"
        : "+f"(c[0]), "+f"(c[1]), "+f"(c[2]), "+f"(c[3])
        : "r"(a.x), "r"(a.y), "r"(a.z), "r"(a.w), "r"(b.x), "r"(b.y));
}

__device__ __forceinline__ void cp16(void* dst, const void* src) {
    uint32_t d = (uint32_t)__cvta_generic_to_shared(dst);
    asm volatile("cp.async.cg.shared.global [%0], [%1], 16;" :: "r"(d), "l"(src));
}
__device__ __forceinline__ void cp_commit() {
    asm volatile("cp.async.commit_group;");
}
template <int N> __device__ __forceinline__ void cp_wait() {
    asm volatile("cp.async.wait_group %0;" :: "n"(N));
}

// ---------------------------------------------------------------------------
// Prepass: pack A [M][K] row-major -> fragment-packed tf32.
// Atom (16 rows x 8 cols) -> 32 lanes x 4 words: lane(gr,gc) holds
// (gr,gc),(gr+8,gc),(gr,gc+4),(gr+8,gc+4). Atom order: row-block-major, k-atom minor.
// ---------------------------------------------------------------------------
__global__ __launch_bounds__(256) void pack_a_kernel(
    const float* __restrict__ in, float* __restrict__ outp, int M, int K)
{
    __shared__ float sm[16][132];
    const int t = threadIdx.x;
    const int am  = blockIdx.y;            // 16-row block
    const int ak0 = blockIdx.x * 16;       // 16 k-atoms = 128 cols
    const float* src = in + (size_t)am * 16 * K + ak0 * 8;
#pragma unroll
    for (int u = 0; u < 8; u++) {
        int idx = u * 256 + t;
        int r = idx >> 7, c = idx & 127;
        sm[r][c] = src[(size_t)r * K + c];
    }
    __syncthreads();
    float* dst = outp + ((size_t)am * (K / 8) + ak0) * 128;
#pragma unroll
    for (int u = 0; u < 2; u++) {
        int c = u * 256 + t;
        int j = c >> 5, lane = c & 31;
        int gr = lane >> 2, gc = lane & 3;
        float4 v;
        v.x = tft(sm[gr][j * 8 + gc]);
        v.y = tft(sm[gr + 8][j * 8 + gc]);
        v.z = tft(sm[gr][j * 8 + gc + 4]);
        v.w = tft(sm[gr + 8][j * 8 + gc + 4]);
        *(float4*)(dst + (size_t)j * 128 + lane * 4) = v;
    }
}

// ---------------------------------------------------------------------------
// Prepass: pack B [K][N] row-major -> fragment-packed tf32.
// Atom (8 k x 8 n) -> 32 lanes x 2 words: lane(gr,gc) holds
// B[k=gc][n=gr], B[k=gc+4][n=gr]. Atom order: k-atom-major, n-atom minor.
// ---------------------------------------------------------------------------
__global__ __launch_bounds__(256) void pack_b_kernel(
    const float* __restrict__ in, float* __restrict__ outp, int K, int N)
{
    __shared__ float sm[32][136];
    const int t = threadIdx.x;
    const int ak0 = blockIdx.y * 4;        // 4 k-atoms = 32 rows
    const int an0 = blockIdx.x * 16;       // 16 n-atoms = 128 cols
    const float* src = in + (size_t)ak0 * 8 * N + an0 * 8;
#pragma unroll
    for (int u = 0; u < 16; u++) {
        int idx = u * 256 + t;
        int r = idx >> 7, c = idx & 127;
        sm[r][c] = src[(size_t)r * N + c];
    }
    __syncthreads();
#pragma unroll
    for (int u = 0; u < 8; u++) {
        int c = u * 256 + t;               // uint2 index, 2048 total
        int ks  = c >> 9;
        int rem = c & 511;
        int an = rem >> 5, lane = rem & 31;
        int gr = lane >> 2, gc = lane & 3;
        float2 v;
        v.x = tft(sm[ks * 8 + gc][an * 8 + gr]);
        v.y = tft(sm[ks * 8 + gc + 4][an * 8 + gr]);
        float* dst = outp + (((size_t)(ak0 + ks) * (N / 8) + an0 + an) * 32 + lane) * 2;
        *(float2*)dst = v;
    }
}

// ---------------------------------------------------------------------------
// TF32 GEMM + bias on PACKED operands. 128x128x32 tile, 256 thr, warp=64Mx32N.
// 3-stage cp.async pipeline; fragment loads are LDS.128 (A) / LDS.64 (B).
// Stage = 16KB A + 16KB B = 32KB; dynamic SMEM = 98304 B.
// ---------------------------------------------------------------------------
template <bool TRUNC_OUT>
__global__ __launch_bounds__(256, 2) void gemm_pk_kernel(
    const float* __restrict__ Ap, const float* __restrict__ Bp,
    const float* __restrict__ bias, float* __restrict__ C,
    int M, int N, int K)
{
    extern __shared__ float smf[];
    char* smb = (char*)smf;

    const int tid  = threadIdx.x;
    const int lane = tid & 31;
    const int warp = tid >> 5;
    const int bm = blockIdx.y * 128;
    const int bn = blockIdx.x * 128;
    const int wm2 = (warp & 1) * 4;        // warp m-atom base (tile-local)
    const int wn2 = (warp >> 1) * 4;       // warp n-atom base (tile-local)
    const int gr = lane >> 2;
    const int gc = lane & 3;
    const int K8 = K / 8, N8 = N / 8;

    auto prefetch = [&](int t, int s) {
        char* Ad = smb + s * 32768;
        char* Bd = Ad + 16384;
#pragma unroll
        for (int u = 0; u < 4; u++) {
            int c = u * 256 + tid;                 // 0..1023
            // A chunk: i = c>>7 (m-atom), j = (c>>5)&3 (k-atom), lane = c&31
            int ai = c >> 7, aj = (c >> 5) & 3, al = c & 31;
            const float* ag = Ap + (((size_t)(bm >> 4) + ai) * K8 + t * 4 + aj) * 128 + al * 4;
            cp16(Ad + c * 16, ag);
            // B chunk: ks = c>>8, contiguous within ks
            int ks = c >> 8, rr = c & 255;
            const float* bg = Bp + (((size_t)(t * 4 + ks)) * N8 + (bn >> 3)) * 64 + rr * 4;
            cp16(Bd + c * 16, bg);
        }
    };

    float c[4][4][4];
#pragma unroll
    for (int i = 0; i < 4; i++)
#pragma unroll
        for (int j = 0; j < 4; j++)
#pragma unroll
            for (int r = 0; r < 4; r++) c[i][j][r] = 0.0f;

    const int nit = K / 32;
    prefetch(0, 0); cp_commit();
    prefetch(1, 1); cp_commit();

    for (int t = 0; t < nit; t++) {
        if (t + 2 < nit) { prefetch(t + 2, (t + 2) % 3); cp_commit(); cp_wait<2>(); }
        else if (t + 1 < nit) cp_wait<1>();
        else cp_wait<0>();
        __syncthreads();

        const char* st = smb + (t % 3) * 32768;
        const uint4* Af = (const uint4*)st;
        const uint2* Bf = (const uint2*)(st + 16384);

#pragma unroll
        for (int ks = 0; ks < 4; ks++) {
            uint4 a4[4];
#pragma unroll
            for (int i = 0; i < 4; i++)
                a4[i] = Af[(((wm2 + i) << 2) + ks) * 32 + lane];
            uint2 b2[4];
#pragma unroll
            for (int j = 0; j < 4; j++)
                b2[j] = Bf[((ks << 4) + wn2 + j) * 32 + lane];
#pragma unroll
            for (int i = 0; i < 4; i++)
#pragma unroll
                for (int j = 0; j < 4; j++)
                    mma_tf32_v(c[i][j], a4[i], b2[j]);
        }
        __syncthreads();
    }

#pragma unroll
    for (int i = 0; i < 4; i++) {
#pragma unroll
        for (int j = 0; j < 4; j++) {
            int row = bm + (wm2 + i) * 16 + gr;
            int col = bn + (wn2 + j) * 8 + 2 * gc;
            float bx = bias[col], by = bias[col + 1];
            float v0 = c[i][j][0] + bx, v1 = c[i][j][1] + by;
            float v2 = c[i][j][2] + bx, v3 = c[i][j][3] + by;
            if (TRUNC_OUT) { v0 = tft(v0); v1 = tft(v1); v2 = tft(v2); v3 = tft(v3); }
            *(float2*)(C + (size_t)row * N + col)       = make_float2(v0, v1);
            *(float2*)(C + (size_t)(row + 8) * N + col) = make_float2(v2, v3);
        }
    }
}

// ---------------------------------------------------------------------------
// Tensor-core causal flash attention (legacy mma), 128-query tiles, cp.async
// double buffer. Epilogue writes PACKED-A layout for the proj GEMM.
// SMEM: QP[128][68] + 2x K[64][68] + 2x V[64][64] = 102400 B.
// ---------------------------------------------------------------------------
__global__ __launch_bounds__(128, 2) void attn_tc_kernel(
    const float* __restrict__ qkv, float* __restrict__ outp)
{
    constexpr int QP = 68;
    extern __shared__ float smf[];
    uint32_t* QPs = (uint32_t*)smf;                 // [128][68]
    float* Kb0 = smf + 128 * QP;
    float* Kb1 = Kb0 + 64 * QP;
    float* Vb0 = Kb1 + 64 * QP;
    float* Vb1 = Vb0 + 64 * 64;

    const int tid  = threadIdx.x;
    const int lane = tid & 31;
    const int w    = tid >> 5;
    const int gr   = lane >> 2;
    const int gc   = lane & 3;
    const int qt = blockIdx.x;
    const int h  = blockIdx.y;
    const int b  = blockIdx.z;
    const size_t rs = QKV_N;
    const int qbase_g = qt * 128;

    auto prefetch = [&](int kt, int pb) {
        const float* kg = qkv + ((size_t)(b * TT + kt * 64)) * rs + DD + h * HDIM;
        const float* vg = kg + DD;
        float* Kd = pb ? Kb1 : Kb0;
        float* Vd = pb ? Vb1 : Vb0;
#pragma unroll
        for (int it = 0; it < 8; it++) {
            int idx = it * 128 + tid;
            int row = idx >> 4;
            int c4  = (idx & 15) * 4;
            cp16(Kd + row * QP + c4, kg + (size_t)row * rs + c4);
            cp16(Vd + row * 64 + (c4 ^ ((row & 3) * 8)), vg + (size_t)row * rs + c4);
        }
    };

    prefetch(0, 0); cp_commit();

    const float* qg = qkv + ((size_t)(b * TT + qbase_g)) * rs + h * HDIM;
#pragma unroll
    for (int it = 0; it < 16; it++) {
        int idx = it * 128 + tid;
        int row = idx >> 4;
        int c4  = (idx & 15) * 4;
        float4 v = *(const float4*)(qg + (size_t)row * rs + c4);
        v.x *= 0.125f; v.y *= 0.125f; v.z *= 0.125f; v.w *= 0.125f;
        *(float4*)&QPs[row * QP + c4] = v;
    }
    __syncthreads();

    uint32_t qf[2][8][4];
#pragma unroll
    for (int mi = 0; mi < 2; mi++) {
        const uint32_t* qb = &QPs[(w * 32 + mi * 16 + gr) * QP + gc];
#pragma unroll
        for (int ks = 0; ks < 8; ks++) {
            qf[mi][ks][0] = qb[ks * 8];
            qf[mi][ks][1] = qb[8 * QP + ks * 8];
            qf[mi][ks][2] = qb[ks * 8 + 4];
            qf[mi][ks][3] = qb[8 * QP + ks * 8 + 4];
        }
    }

    float o[2][8][4];
#pragma unroll
    for (int mi = 0; mi < 2; mi++)
#pragma unroll
        for (int j = 0; j < 8; j++)
#pragma unroll
            for (int r = 0; r < 4; r++) o[mi][j][r] = 0.0f;
    float mS[2][2] = {{-1e30f, -1e30f}, {-1e30f, -1e30f}};
    float lS[2][2] = {{0.0f, 0.0f}, {0.0f, 0.0f}};

    const int ntiles = 2 * qt + 2;
    for (int kt = 0; kt < ntiles; kt++) {
        if (kt + 1 < ntiles) { prefetch(kt + 1, (kt + 1) & 1); cp_commit(); cp_wait<1>(); }
        else cp_wait<0>();
        __syncthreads();
        const uint32_t* Kf = (const uint32_t*)((kt & 1) ? Kb1 : Kb0);
        const uint32_t* Vf = (const uint32_t*)((kt & 1) ? Vb1 : Vb0);

#pragma unroll
        for (int mi = 0; mi < 2; mi++) {
            const int wbase_g = qbase_g + w * 32 + mi * 16;
            if (kt * 64 > wbase_g) continue;

            float s[8][4];
#pragma unroll
            for (int j = 0; j < 8; j++) {
                s[j][0] = s[j][1] = s[j][2] = s[j][3] = 0.0f;
                const uint32_t* kb2 = &Kf[(j * 8 + gr) * QP + gc];
#pragma unroll
                for (int ks = 0; ks < 8; ks++)
                    mma_tf32(s[j], qf[mi][ks], kb2[ks * 8], kb2[ks * 8 + 4]);
            }

            if (kt * 64 + 63 > wbase_g) {
                const int row0 = wbase_g + gr;
                const int row1 = row0 + 8;
#pragma unroll
                for (int j = 0; j < 8; j++) {
                    int key0 = kt * 64 + j * 8 + 2 * gc;
                    if (key0     > row0) s[j][0] = -1e30f;
                    if (key0 + 1 > row0) s[j][1] = -1e30f;
                    if (key0     > row1) s[j][2] = -1e30f;
                    if (key0 + 1 > row1) s[j][3] = -1e30f;
                }
            }

            float mx0 = -1e30f, mx1 = -1e30f;
#pragma unroll
            for (int j = 0; j < 8; j++) {
                mx0 = fmaxf(mx0, fmaxf(s[j][0], s[j][1]));
                mx1 = fmaxf(mx1, fmaxf(s[j][2], s[j][3]));
            }
            mx0 = fmaxf(mx0, __shfl_xor_sync(0xffffffffu, mx0, 1));
            mx0 = fmaxf(mx0, __shfl_xor_sync(0xffffffffu, mx0, 2));
            mx1 = fmaxf(mx1, __shfl_xor_sync(0xffffffffu, mx1, 1));
            mx1 = fmaxf(mx1, __shfl_xor_sync(0xffffffffu, mx1, 2));

            float mn0 = fmaxf(mS[mi][0], mx0), mn1 = fmaxf(mS[mi][1], mx1);
            float cr0 = __expf(mS[mi][0] - mn0), cr1 = __expf(mS[mi][1] - mn1);
            lS[mi][0] *= cr0; lS[mi][1] *= cr1;
#pragma unroll
            for (int j = 0; j < 8; j++) {
                o[mi][j][0] *= cr0; o[mi][j][1] *= cr0;
                o[mi][j][2] *= cr1; o[mi][j][3] *= cr1;
            }

            float rs0 = 0.0f, rs1 = 0.0f;
            uint32_t* prow = &QPs[(w * 32 + mi * 16 + gr) * QP + 2 * gc];
#pragma unroll
            for (int j = 0; j < 8; j++) {
                float p0 = __expf(s[j][0] - mn0);
                float p1 = __expf(s[j][1] - mn0);
                float p2 = __expf(s[j][2] - mn1);
                float p3 = __expf(s[j][3] - mn1);
                rs0 += p0 + p1; rs1 += p2 + p3;
                *(uint2*)&prow[j * 8]          = make_uint2(f2tf32(p0), f2tf32(p1));
                *(uint2*)&prow[8 * QP + j * 8] = make_uint2(f2tf32(p2), f2tf32(p3));
            }
            rs0 += __shfl_xor_sync(0xffffffffu, rs0, 1);
            rs0 += __shfl_xor_sync(0xffffffffu, rs0, 2);
            rs1 += __shfl_xor_sync(0xffffffffu, rs1, 1);
            rs1 += __shfl_xor_sync(0xffffffffu, rs1, 2);
            lS[mi][0] += rs0; lS[mi][1] += rs1;
            mS[mi][0] = mn0; mS[mi][1] = mn1;
            __syncwarp();

            uint32_t pf[8][4];
            {
                const uint32_t* pb = &QPs[(w * 32 + mi * 16 + gr) * QP + gc];
#pragma unroll
                for (int kc = 0; kc < 8; kc++) {
                    pf[kc][0] = pb[kc * 8];
                    pf[kc][1] = pb[8 * QP + kc * 8];
                    pf[kc][2] = pb[kc * 8 + 4];
                    pf[kc][3] = pb[8 * QP + kc * 8 + 4];
                }
            }

#pragma unroll
            for (int j = 0; j < 8; j++) {
                const int csw = (j * 8 + gr) ^ (gc * 8);
#pragma unroll
                for (int kc = 0; kc < 8; kc++)
                    mma_tf32(o[mi][j], pf[kc],
                             Vf[(kc * 8 + gc) * 64 + csw],
                             Vf[(kc * 8 + gc + 4) * 64 + csw]);
            }
        }
        __syncthreads();
    }

    // ---- epilogue: normalize + write PACKED-A layout (tf32-truncated) ----
    // Packed A: atom (16q x 8col), lane(gr',gc') holds (gr',gc'),(gr'+8,gc'),
    // (gr',gc'+4),(gr'+8,gc'+4). This lane owns cols 2gc,2gc+1 of rows gr,gr+8.
    const int lp  = gr * 4 + ((2 * gc) & 3);   // packed lane for col 2gc
    const int hi  = (gc >= 2);                 // upper half -> words 2/3
    const int w02 = hi ? 2 : 0;
    const int w13 = hi ? 3 : 1;
#pragma unroll
    for (int mi = 0; mi < 2; mi++) {
        float iv0 = 1.0f / lS[mi][0], iv1 = 1.0f / lS[mi][1];
        int rowg = b * TT + qbase_g + w * 32 + mi * 16;     // 16-aligned
        size_t am = (size_t)(rowg >> 4);
        float* base = outp + (am * (DD / 8) + h * 8) * 128; // atom = 128 floats
#pragma unroll
        for (int j = 0; j < 8; j++) {
            float* at = base + j * 128 + lp * 4;
            at[w02]     = tft(o[mi][j][0] * iv0);
            at[4 + w02] = tft(o[mi][j][1] * iv0);
            at[w13]     = tft(o[mi][j][2] * iv1);
            at[4 + w13] = tft(o[mi][j][3] * iv1);
        }
    }
}

// ---------------------------------------------------------------------------
// Launch
// ---------------------------------------------------------------------------
extern "C" void kernel_launch(void* const* d_in, const int* in_sizes, int n_in,
                              void* d_out, int out_size)
{
    const float* x      = (const float*)d_in[0];
    const float* qkv_w  = (const float*)d_in[1];
    const float* qkv_b  = (const float*)d_in[2];
    const float* proj_w = (const float*)d_in[3];
    const float* proj_b = (const float*)d_in[4];
    float* out = (float*)d_out;

    float *qkv_s, *att_s, *xt, *wqkv, *wproj;
    cudaGetSymbolAddress((void**)&qkv_s, g_qkv);
    cudaGetSymbolAddress((void**)&att_s, g_att);
    cudaGetSymbolAddress((void**)&xt,    g_xt);
    cudaGetSymbolAddress((void**)&wqkv,  g_wqkv);
    cudaGetSymbolAddress((void**)&wproj, g_wproj);

    const int GEMM_SMEM = 3 * 32768;                                  // 98304
    const int ATTN_SMEM = (128 * 68 + 2 * 64 * 68 + 2 * 64 * 64) * sizeof(float); // 102400
    cudaFuncSetAttribute(gemm_pk_kernel<true>,
                         cudaFuncAttributeMaxDynamicSharedMemorySize, GEMM_SMEM);
    cudaFuncSetAttribute(gemm_pk_kernel<false>,
                         cudaFuncAttributeMaxDynamicSharedMemorySize, GEMM_SMEM);
    cudaFuncSetAttribute(attn_tc_kernel,
                         cudaFuncAttributeMaxDynamicSharedMemorySize, ATTN_SMEM);

    // 0) Prepass: pack+truncate x (A) and both weights (B)
    pack_a_kernel<<<dim3(DD / 128, MROWS / 16), 256>>>(x, xt, MROWS, DD);
    pack_b_kernel<<<dim3(QKV_N / 128, DD / 32), 256>>>(qkv_w, wqkv, DD, QKV_N);
    pack_b_kernel<<<dim3(DD / 128, DD / 32), 256>>>(proj_w, wproj, DD, DD);

    // 1) QKV GEMM (packed operands) -> row-major truncated QKV
    dim3 g1(QKV_N / 128, MROWS / 128);
    gemm_pk_kernel<true><<<g1, 256, GEMM_SMEM>>>(xt, wqkv, qkv_b, qkv_s,
                                                 MROWS, QKV_N, DD);

    // 2) Causal multi-head attention -> packed-A attention output
    dim3 ga(TT / 128, HH, BB);
    attn_tc_kernel<<<ga, 128, ATTN_SMEM>>>(qkv_s, att_s);

    // 3) Output projection (packed operands) -> final row-major output
    dim3 g2(DD / 128, MROWS / 128);
    gemm_pk_kernel<false><<<g2, 256, GEMM_SMEM>>>(att_s, wproj, proj_b, out,
                                                  MROWS, DD, DD);
}

// round 9
// speedup vs baseline: 1.2916x; 1.0300x over previous
#include <cuda_runtime.h>
#include <cstdint>

// Problem constants
#define BB 4
#define TT 2048
#define DD 1024
#define HH 16
#define HDIM 64
#define MROWS (BB * TT)            // 8192
#define QKV_N (3 * DD)             // 3072

// Scratch (allocation-free rule: __device__ globals)
__device__ float g_qp[(size_t)MROWS * DD];       // 32 MB packed-A Q (x0.125, tf32)
__device__ float g_kp[(size_t)MROWS * DD];       // 32 MB packed-B K (QK layout)
__device__ float g_vp[(size_t)MROWS * DD];       // 32 MB packed-B V (PV layout)
__device__ float g_att[(size_t)MROWS * DD];      // 32 MB packed-A attention output
__device__ float g_xt[(size_t)MROWS * DD];       // 32 MB packed-A truncated x
__device__ float g_wqkv[(size_t)DD * QKV_N];     // 12 MB packed-B qkv_w
__device__ float g_wproj[(size_t)DD * DD];       //  4 MB packed-B proj_w

__device__ __forceinline__ uint32_t f2tf32(float x) {
    uint32_t u;
    asm("cvt.rna.tf32.f32 %0, %1;" : "=r"(u) : "f"(x));
    return u;
}
__device__ __forceinline__ float tft(float x) { return __uint_as_float(f2tf32(x)); }

__device__ __forceinline__ void mma_tf32_v(float c[4], uint4 a, uint2 b) {
    asm volatile(
        "mma.sync.aligned.m16n8k8.row.col.f32.tf32.tf32.f32 "
        "{%0,%1,%2,%3}, {%4,%5,%6,%7}, {%8,%9}, {%0,%1,%2,%3};"
        : "+f"(c[0]), "+f"(c[1]), "+f"(c[2]), "+f"(c[3])
        : "r"(a.x), "r"(a.y), "r"(a.z), "r"(a.w), "r"(b.x), "r"(b.y));
}

__device__ __forceinline__ void cp16(void* dst, const void* src) {
    uint32_t d = (uint32_t)__cvta_generic_to_shared(dst);
    asm volatile("cp.async.cg.shared.global [%0], [%1], 16;" :: "r"(d), "l"(src));
}
__device__ __forceinline__ void cp_commit() {
    asm volatile("cp.async.commit_group;");
}
template <int N> __device__ __forceinline__ void cp_wait() {
    asm volatile("cp.async.wait_group %0;" :: "n"(N));
}

// ---------------------------------------------------------------------------
// Prepass: pack A [M][K] row-major -> fragment-packed tf32. (unchanged R8)
// ---------------------------------------------------------------------------
__global__ __launch_bounds__(256) void pack_a_kernel(
    const float* __restrict__ in, float* __restrict__ outp, int M, int K)
{
    __shared__ float sm[16][132];
    const int t = threadIdx.x;
    const int am  = blockIdx.y;
    const int ak0 = blockIdx.x * 16;
    const float* src = in + (size_t)am * 16 * K + ak0 * 8;
#pragma unroll
    for (int u = 0; u < 8; u++) {
        int idx = u * 256 + t;
        int r = idx >> 7, c = idx & 127;
        sm[r][c] = src[(size_t)r * K + c];
    }
    __syncthreads();
    float* dst = outp + ((size_t)am * (K / 8) + ak0) * 128;
#pragma unroll
    for (int u = 0; u < 2; u++) {
        int c = u * 256 + t;
        int j = c >> 5, lane = c & 31;
        int gr = lane >> 2, gc = lane & 3;
        float4 v;
        v.x = tft(sm[gr][j * 8 + gc]);
        v.y = tft(sm[gr + 8][j * 8 + gc]);
        v.z = tft(sm[gr][j * 8 + gc + 4]);
        v.w = tft(sm[gr + 8][j * 8 + gc + 4]);
        *(float4*)(dst + (size_t)j * 128 + lane * 4) = v;
    }
}

// ---------------------------------------------------------------------------
// Prepass: pack B [K][N] row-major -> fragment-packed tf32. (unchanged R8)
// ---------------------------------------------------------------------------
__global__ __launch_bounds__(256) void pack_b_kernel(
    const float* __restrict__ in, float* __restrict__ outp, int K, int N)
{
    __shared__ float sm[32][136];
    const int t = threadIdx.x;
    const int ak0 = blockIdx.y * 4;
    const int an0 = blockIdx.x * 16;
    const float* src = in + (size_t)ak0 * 8 * N + an0 * 8;
#pragma unroll
    for (int u = 0; u < 16; u++) {
        int idx = u * 256 + t;
        int r = idx >> 7, c = idx & 127;
        sm[r][c] = src[(size_t)r * N + c];
    }
    __syncthreads();
#pragma unroll
    for (int u = 0; u < 8; u++) {
        int c = u * 256 + t;
        int ks  = c >> 9;
        int rem = c & 511;
        int an = rem >> 5, lane = rem & 31;
        int gr = lane >> 2, gc = lane & 3;
        float2 v;
        v.x = tft(sm[ks * 8 + gc][an * 8 + gr]);
        v.y = tft(sm[ks * 8 + gc + 4][an * 8 + gr]);
        float* dst = outp + (((size_t)(ak0 + ks) * (N / 8) + an0 + an) * 32 + lane) * 2;
        *(float2*)dst = v;
    }
}

// ---------------------------------------------------------------------------
// TF32 GEMM on PACKED operands (mainloop identical to R8).
// MODE 0: row-major C + bias (proj). MODE 2: scatter to packed Q/K/V (QKV).
// ---------------------------------------------------------------------------
template <int MODE>
__global__ __launch_bounds__(256, 2) void gemm_pk_kernel(
    const float* __restrict__ Ap, const float* __restrict__ Bp,
    const float* __restrict__ bias, float* __restrict__ C,
    float* __restrict__ qp, float* __restrict__ kp, float* __restrict__ vp,
    int M, int N, int K)
{
    extern __shared__ float smf[];
    char* smb = (char*)smf;

    const int tid  = threadIdx.x;
    const int lane = tid & 31;
    const int warp = tid >> 5;
    const int bm = blockIdx.y * 128;
    const int bn = blockIdx.x * 128;
    const int wm2 = (warp & 1) * 4;
    const int wn2 = (warp >> 1) * 4;
    const int gr = lane >> 2;
    const int gc = lane & 3;
    const int K8 = K / 8, N8 = N / 8;

    auto prefetch = [&](int t, int s) {
        char* Ad = smb + s * 32768;
        char* Bd = Ad + 16384;
#pragma unroll
        for (int u = 0; u < 4; u++) {
            int c = u * 256 + tid;
            int ai = c >> 7, aj = (c >> 5) & 3, al = c & 31;
            const float* ag = Ap + (((size_t)(bm >> 4) + ai) * K8 + t * 4 + aj) * 128 + al * 4;
            cp16(Ad + c * 16, ag);
            int ks = c >> 8, rr = c & 255;
            const float* bg = Bp + (((size_t)(t * 4 + ks)) * N8 + (bn >> 3)) * 64 + rr * 4;
            cp16(Bd + c * 16, bg);
        }
    };

    float c[4][4][4];
#pragma unroll
    for (int i = 0; i < 4; i++)
#pragma unroll
        for (int j = 0; j < 4; j++)
#pragma unroll
            for (int r = 0; r < 4; r++) c[i][j][r] = 0.0f;

    const int nit = K / 32;
    prefetch(0, 0); cp_commit();
    prefetch(1, 1); cp_commit();

    for (int t = 0; t < nit; t++) {
        if (t + 2 < nit) { prefetch(t + 2, (t + 2) % 3); cp_commit(); cp_wait<2>(); }
        else if (t + 1 < nit) cp_wait<1>();
        else cp_wait<0>();
        __syncthreads();

        const char* st = smb + (t % 3) * 32768;
        const uint4* Af = (const uint4*)st;
        const uint2* Bf = (const uint2*)(st + 16384);

#pragma unroll
        for (int ks = 0; ks < 4; ks++) {
            uint4 a4[4];
#pragma unroll
            for (int i = 0; i < 4; i++)
                a4[i] = Af[(((wm2 + i) << 2) + ks) * 32 + lane];
            uint2 b2[4];
#pragma unroll
            for (int j = 0; j < 4; j++)
                b2[j] = Bf[((ks << 4) + wn2 + j) * 32 + lane];
#pragma unroll
            for (int i = 0; i < 4; i++)
#pragma unroll
                for (int j = 0; j < 4; j++)
                    mma_tf32_v(c[i][j], a4[i], b2[j]);
        }
        __syncthreads();
    }

    if (MODE == 0) {
#pragma unroll
        for (int i = 0; i < 4; i++) {
#pragma unroll
            for (int j = 0; j < 4; j++) {
                int row = bm + (wm2 + i) * 16 + gr;
                int col = bn + (wn2 + j) * 8 + 2 * gc;
                float bx = bias[col], by = bias[col + 1];
                *(float2*)(C + (size_t)row * N + col) =
                    make_float2(c[i][j][0] + bx, c[i][j][1] + by);
                *(float2*)(C + (size_t)(row + 8) * N + col) =
                    make_float2(c[i][j][2] + bx, c[i][j][3] + by);
            }
        }
    } else {
        // Scatter-write packed Q (A-frag atoms, x0.125) / K (B-QK) / V (B-PV).
        const int sec = bn >> 10;                // block is entirely in one section
        auto wr = [&](float val, int row, int col) {
            float v = tft(val + bias[col]);
            int h = (col & 1023) >> 6, d = col & 63;
            int b = row >> 11, tt = row & 2047;
            int bh = b * HH + h;
            if (sec == 0) {
                size_t a = (((size_t)bh * 128 + (tt >> 4)) * 8 + (d >> 3)) * 128
                         + ((tt & 7) * 4 + (d & 3)) * 4 + ((tt >> 3) & 1) + 2 * ((d >> 2) & 1);
                qp[a] = v * 0.125f;
            } else if (sec == 1) {
                size_t a = ((((size_t)bh * 32 + (tt >> 6)) * 8 + ((tt >> 3) & 7)) * 8 + (d >> 3)) * 64
                         + ((tt & 7) * 4 + (d & 3)) * 2 + ((d >> 2) & 1);
                kp[a] = v;
            } else {
                size_t a = ((((size_t)bh * 32 + (tt >> 6)) * 8 + ((tt >> 3) & 7)) * 8 + (d >> 3)) * 64
                         + ((d & 7) * 4 + (tt & 3)) * 2 + ((tt >> 2) & 1);
                vp[a] = v;
            }
        };
#pragma unroll
        for (int i = 0; i < 4; i++) {
#pragma unroll
            for (int j = 0; j < 4; j++) {
                int row = bm + (wm2 + i) * 16 + gr;
                int col = bn + (wn2 + j) * 8 + 2 * gc;
                wr(c[i][j][0], row,     col);
                wr(c[i][j][1], row,     col + 1);
                wr(c[i][j][2], row + 8, col);
                wr(c[i][j][3], row + 8, col + 1);
            }
        }
    }
}

// ---------------------------------------------------------------------------
// Causal flash attention on PACKED operands.
// 128 thr / 4 warps, 128-query tiles (2x16-row chunks per warp).
// Q frags via LDG.128; K/V tiles = contiguous 16KB cp.async; P packed in SMEM.
// SMEM: P[8 chunks][8 atoms][512B] = 32KB + 2x(K 16KB) + 2x(V 16KB) = 96KB.
// ---------------------------------------------------------------------------
__global__ __launch_bounds__(128, 2) void attn_pk_kernel(
    const float* __restrict__ qp, const float* __restrict__ kp,
    const float* __restrict__ vp, float* __restrict__ outp)
{
    extern __shared__ float smf[];
    float* Pp  = smf;                  // 8192 floats
    float* Kb0 = smf + 8192;           // 4096 floats each
    float* Kb1 = Kb0 + 4096;
    float* Vb0 = Kb1 + 4096;
    float* Vb1 = Vb0 + 4096;

    const int tid  = threadIdx.x;
    const int lane = tid & 31;
    const int w    = tid >> 5;
    const int gr   = lane >> 2;
    const int gc   = lane & 3;
    const int qt = gridDim.x - 1 - blockIdx.x;   // heavy blocks first
    const int h  = blockIdx.y;
    const int b  = blockIdx.z;
    const int bh = b * HH + h;
    const int qbase_g = qt * 128;

    const float* kbase = kp + (size_t)bh * 32 * 4096;
    const float* vbase = vp + (size_t)bh * 32 * 4096;

    auto prefetch = [&](int kt, int pb) {
        float* Kd = pb ? Kb1 : Kb0;
        float* Vd = pb ? Vb1 : Vb0;
        const float* ks = kbase + (size_t)kt * 4096;
        const float* vs = vbase + (size_t)kt * 4096;
#pragma unroll
        for (int u = 0; u < 8; u++) {
            int c = u * 128 + tid;                // 0..1023 16B chunks
            cp16((char*)Kd + c * 16, ks + c * 4);
            cp16((char*)Vd + c * 16, vs + c * 4);
        }
    };

    prefetch(0, 0); cp_commit();

    // ---- Q fragments: direct LDG.128 from packed Q ----
    uint4 qf[2][8];
#pragma unroll
    for (int mi = 0; mi < 2; mi++) {
        const uint4* qg = (const uint4*)(qp
            + (((size_t)bh * 128 + qt * 8 + w * 2 + mi) * 8) * 128) + lane;
#pragma unroll
        for (int ks = 0; ks < 8; ks++)
            qf[mi][ks] = qg[ks * 32];
    }

    float o[2][8][4];
#pragma unroll
    for (int mi = 0; mi < 2; mi++)
#pragma unroll
        for (int j = 0; j < 8; j++)
#pragma unroll
            for (int r = 0; r < 4; r++) o[mi][j][r] = 0.0f;
    float mS[2][2] = {{-1e30f, -1e30f}, {-1e30f, -1e30f}};
    float lS[2][2] = {{0.0f, 0.0f}, {0.0f, 0.0f}};

    const int ntiles = 2 * qt + 2;
    for (int kt = 0; kt < ntiles; kt++) {
        if (kt + 1 < ntiles) { prefetch(kt + 1, (kt + 1) & 1); cp_commit(); cp_wait<1>(); }
        else cp_wait<0>();
        __syncthreads();
        const uint2* Kf = (const uint2*)((kt & 1) ? Kb1 : Kb0);
        const uint2* Vf = (const uint2*)((kt & 1) ? Vb1 : Vb0);

#pragma unroll
        for (int mi = 0; mi < 2; mi++) {
            const int wbase_g = qbase_g + w * 32 + mi * 16;
            if (kt * 64 > wbase_g) continue;   // chunk fully masked

            // ---- S = Q @ K^T (packed K: LDS.64 frags) ----
            float s[8][4];
#pragma unroll
            for (int j = 0; j < 8; j++) {
                s[j][0] = s[j][1] = s[j][2] = s[j][3] = 0.0f;
#pragma unroll
                for (int ks = 0; ks < 8; ks++)
                    mma_tf32_v(s[j], qf[mi][ks], Kf[(j * 8 + ks) * 32 + lane]);
            }

            // ---- causal mask (boundary tiles only) ----
            if (kt * 64 + 63 > wbase_g) {
                const int row0 = wbase_g + gr;
                const int row1 = row0 + 8;
#pragma unroll
                for (int j = 0; j < 8; j++) {
                    int key0 = kt * 64 + j * 8 + 2 * gc;
                    if (key0     > row0) s[j][0] = -1e30f;
                    if (key0 + 1 > row0) s[j][1] = -1e30f;
                    if (key0     > row1) s[j][2] = -1e30f;
                    if (key0 + 1 > row1) s[j][3] = -1e30f;
                }
            }

            // ---- online softmax ----
            float mx0 = -1e30f, mx1 = -1e30f;
#pragma unroll
            for (int j = 0; j < 8; j++) {
                mx0 = fmaxf(mx0, fmaxf(s[j][0], s[j][1]));
                mx1 = fmaxf(mx1, fmaxf(s[j][2], s[j][3]));
            }
            mx0 = fmaxf(mx0, __shfl_xor_sync(0xffffffffu, mx0, 1));
            mx0 = fmaxf(mx0, __shfl_xor_sync(0xffffffffu, mx0, 2));
            mx1 = fmaxf(mx1, __shfl_xor_sync(0xffffffffu, mx1, 1));
            mx1 = fmaxf(mx1, __shfl_xor_sync(0xffffffffu, mx1, 2));

            float mn0 = fmaxf(mS[mi][0], mx0), mn1 = fmaxf(mS[mi][1], mx1);
            float cr0 = __expf(mS[mi][0] - mn0), cr1 = __expf(mS[mi][1] - mn1);
            lS[mi][0] *= cr0; lS[mi][1] *= cr1;
#pragma unroll
            for (int j = 0; j < 8; j++) {
                o[mi][j][0] *= cr0; o[mi][j][1] *= cr0;
                o[mi][j][2] *= cr1; o[mi][j][3] *= cr1;
            }

            // ---- exp + packed-P write (2x STS.64 per key atom) ----
            float rs0 = 0.0f, rs1 = 0.0f;
            float* pbase = Pp + ((w * 2 + mi) * 8) * 128;
            const int lane0w = (gr * 4 + ((2 * gc) & 3)) * 4 + 2 * (gc >> 1);
#pragma unroll
            for (int j = 0; j < 8; j++) {
                float p0 = __expf(s[j][0] - mn0);
                float p1 = __expf(s[j][1] - mn0);
                float p2 = __expf(s[j][2] - mn1);
                float p3 = __expf(s[j][3] - mn1);
                rs0 += p0 + p1; rs1 += p2 + p3;
                float* at = pbase + j * 128;
                *(uint2*)(at + lane0w)     = make_uint2(f2tf32(p0), f2tf32(p2));
                *(uint2*)(at + lane0w + 4) = make_uint2(f2tf32(p1), f2tf32(p3));
            }
            rs0 += __shfl_xor_sync(0xffffffffu, rs0, 1);
            rs0 += __shfl_xor_sync(0xffffffffu, rs0, 2);
            rs1 += __shfl_xor_sync(0xffffffffu, rs1, 1);
            rs1 += __shfl_xor_sync(0xffffffffu, rs1, 2);
            lS[mi][0] += rs0; lS[mi][1] += rs1;
            mS[mi][0] = mn0; mS[mi][1] = mn1;
            __syncwarp();   // P atoms are warp-private

            // ---- P fragments: LDS.128 ----
            uint4 pf[8];
            const uint4* pb4 = (const uint4*)pbase + lane;
#pragma unroll
            for (int kc = 0; kc < 8; kc++)
                pf[kc] = pb4[kc * 32];

            // ---- O += P @ V (packed V: LDS.64 frags) ----
#pragma unroll
            for (int j = 0; j < 8; j++)
#pragma unroll
                for (int kc = 0; kc < 8; kc++)
                    mma_tf32_v(o[mi][j], pf[kc], Vf[(kc * 8 + j) * 32 + lane]);
        }
        __syncthreads();
    }

    // ---- epilogue: normalize + write PACKED-A for proj (unchanged R8) ----
    const int lp  = gr * 4 + ((2 * gc) & 3);
    const int hi  = (gc >= 2);
    const int w02 = hi ? 2 : 0;
    const int w13 = hi ? 3 : 1;
#pragma unroll
    for (int mi = 0; mi < 2; mi++) {
        float iv0 = 1.0f / lS[mi][0], iv1 = 1.0f / lS[mi][1];
        int rowg = b * TT + qbase_g + w * 32 + mi * 16;
        size_t am = (size_t)(rowg >> 4);
        float* base = outp + (am * (DD / 8) + h * 8) * 128;
#pragma unroll
        for (int j = 0; j < 8; j++) {
            float* at = base + j * 128 + lp * 4;
            at[w02]     = tft(o[mi][j][0] * iv0);
            at[4 + w02] = tft(o[mi][j][1] * iv0);
            at[w13]     = tft(o[mi][j][2] * iv1);
            at[4 + w13] = tft(o[mi][j][3] * iv1);
        }
    }
}

// ---------------------------------------------------------------------------
// Launch
// ---------------------------------------------------------------------------
extern "C" void kernel_launch(void* const* d_in, const int* in_sizes, int n_in,
                              void* d_out, int out_size)
{
    const float* x      = (const float*)d_in[0];
    const float* qkv_w  = (const float*)d_in[1];
    const float* qkv_b  = (const float*)d_in[2];
    const float* proj_w = (const float*)d_in[3];
    const float* proj_b = (const float*)d_in[4];
    float* out = (float*)d_out;

    float *qp, *kpp, *vpp, *att_s, *xt, *wqkv, *wproj;
    cudaGetSymbolAddress((void**)&qp,    g_qp);
    cudaGetSymbolAddress((void**)&kpp,   g_kp);
    cudaGetSymbolAddress((void**)&vpp,   g_vp);
    cudaGetSymbolAddress((void**)&att_s, g_att);
    cudaGetSymbolAddress((void**)&xt,    g_xt);
    cudaGetSymbolAddress((void**)&wqkv,  g_wqkv);
    cudaGetSymbolAddress((void**)&wproj, g_wproj);

    const int GEMM_SMEM = 3 * 32768;                 // 98304
    const int ATTN_SMEM = (8192 + 4 * 4096) * 4;     // 98304
    cudaFuncSetAttribute(gemm_pk_kernel<2>,
                         cudaFuncAttributeMaxDynamicSharedMemorySize, GEMM_SMEM);
    cudaFuncSetAttribute(gemm_pk_kernel<0>,
                         cudaFuncAttributeMaxDynamicSharedMemorySize, GEMM_SMEM);
    cudaFuncSetAttribute(attn_pk_kernel,
                         cudaFuncAttributeMaxDynamicSharedMemorySize, ATTN_SMEM);

    // 0) Prepass: pack+truncate x (A) and both weights (B)
    pack_a_kernel<<<dim3(DD / 128, MROWS / 16), 256>>>(x, xt, MROWS, DD);
    pack_b_kernel<<<dim3(QKV_N / 128, DD / 32), 256>>>(qkv_w, wqkv, DD, QKV_N);
    pack_b_kernel<<<dim3(DD / 128, DD / 32), 256>>>(proj_w, wproj, DD, DD);

    // 1) QKV GEMM -> packed Q / K / V directly
    dim3 g1(QKV_N / 128, MROWS / 128);
    gemm_pk_kernel<2><<<g1, 256, GEMM_SMEM>>>(xt, wqkv, qkv_b, nullptr,
                                              qp, kpp, vpp, MROWS, QKV_N, DD);

    // 2) Causal multi-head attention on packed operands
    dim3 ga(TT / 128, HH, BB);
    attn_pk_kernel<<<ga, 128, ATTN_SMEM>>>(qp, kpp, vpp, att_s);

    // 3) Output projection (packed in, row-major out)
    dim3 g2(DD / 128, MROWS / 128);
    gemm_pk_kernel<0><<<g2, 256, GEMM_SMEM>>>(att_s, wproj, proj_b, out,
                                              nullptr, nullptr, nullptr,
                                              MROWS, DD, DD);
}

// round 10
// speedup vs baseline: 2.3543x; 1.8228x over previous
#include <cuda_runtime.h>
#include <cuda_fp16.h>
#include <cstdint>

// Problem constants
#define BB 4
#define TT 2048
#define DD 1024
#define HH 16
#define HDIM 64
#define MROWS (BB * TT)            // 8192
#define QKV_N (3 * DD)             // 3072

// Scratch (allocation-free rule: __device__ globals) — all fp16 packed
__device__ __half g_qp[(size_t)MROWS * DD];      // 16 MB packed-A Q (x0.125)
__device__ __half g_kp[(size_t)MROWS * DD];      // 16 MB packed-B K (QK layout)
__device__ __half g_vp[(size_t)MROWS * DD];      // 16 MB packed-B V (PV layout)
__device__ __half g_att[(size_t)MROWS * DD];     // 16 MB packed-A attention out
__device__ __half g_xt[(size_t)MROWS * DD];      // 16 MB packed-A x
__device__ __half g_wqkv[(size_t)DD * QKV_N];    //  6 MB packed-B qkv_w
__device__ __half g_wproj[(size_t)DD * DD];      //  2 MB packed-B proj_w

__device__ __forceinline__ uint32_t h2u(float a, float b) {
    __half2 h = __floats2half2_rn(a, b);
    return *reinterpret_cast<uint32_t*>(&h);
}

__device__ __forceinline__ void mma_f16(float c[4], uint4 a, uint2 b) {
    asm volatile(
        "mma.sync.aligned.m16n8k16.row.col.f32.f16.f16.f32 "
        "{%0,%1,%2,%3}, {%4,%5,%6,%7}, {%8,%9}, {%0,%1,%2,%3};"
        : "+f"(c[0]), "+f"(c[1]), "+f"(c[2]), "+f"(c[3])
        : "r"(a.x), "r"(a.y), "r"(a.z), "r"(a.w), "r"(b.x), "r"(b.y));
}

__device__ __forceinline__ void cp16(void* dst, const void* src) {
    uint32_t d = (uint32_t)__cvta_generic_to_shared(dst);
    asm volatile("cp.async.cg.shared.global [%0], [%1], 16;" :: "r"(d), "l"(src));
}
__device__ __forceinline__ void cp_commit() {
    asm volatile("cp.async.commit_group;");
}
template <int N> __device__ __forceinline__ void cp_wait() {
    asm volatile("cp.async.wait_group %0;" :: "n"(N));
}

// ---------------------------------------------------------------------------
// Prepass: pack A [M][K] fp32 row-major -> fp16 A-atoms (16r x 16k, 512B).
// Lane(gr,gc): w0=(gr,2gc,2gc+1) w1=(gr+8,..) w2=(gr,2gc+8,+9) w3=(gr+8,..).
// ---------------------------------------------------------------------------
__global__ __launch_bounds__(256) void pack_a16_kernel(
    const float* __restrict__ in, uint4* __restrict__ outp, int M, int K)
{
    __shared__ float sm[16][132];
    const int t = threadIdx.x;
    const int am  = blockIdx.y;            // 16-row block
    const int ak0 = blockIdx.x * 8;        // 8 k-atoms = 128 cols
    const float* src = in + (size_t)am * 16 * K + ak0 * 16;
#pragma unroll
    for (int u = 0; u < 8; u++) {
        int idx = u * 256 + t;
        int r = idx >> 7, c = idx & 127;
        sm[r][c] = src[(size_t)r * K + c];
    }
    __syncthreads();
    const int j = t >> 5, lane = t & 31;
    const int gr = lane >> 2, gc = lane & 3;
    const int k0 = j * 16;
    uint4 v;
    v.x = h2u(sm[gr][k0 + 2 * gc],     sm[gr][k0 + 2 * gc + 1]);
    v.y = h2u(sm[gr + 8][k0 + 2 * gc], sm[gr + 8][k0 + 2 * gc + 1]);
    v.z = h2u(sm[gr][k0 + 2 * gc + 8], sm[gr][k0 + 2 * gc + 9]);
    v.w = h2u(sm[gr + 8][k0 + 2 * gc + 8], sm[gr + 8][k0 + 2 * gc + 9]);
    outp[((size_t)am * (K >> 4) + ak0 + j) * 32 + lane] = v;
}

// ---------------------------------------------------------------------------
// Prepass: pack B [K][N] fp32 row-major -> fp16 B-atoms (16k x 8n, 256B).
// Lane(gr,gc): b0=(k=2gc,2gc+1 ; n=gr)  b1=(k=2gc+8,2gc+9 ; n=gr).
// ---------------------------------------------------------------------------
__global__ __launch_bounds__(256) void pack_b16_kernel(
    const float* __restrict__ in, uint2* __restrict__ outp, int K, int N)
{
    __shared__ float sm[16][260];
    const int t = threadIdx.x;
    const int ak  = blockIdx.y;            // k-atom row (16 k)
    const int an0 = blockIdx.x * 32;       // 32 n-atoms = 256 cols
    const float* src = in + (size_t)ak * 16 * N + an0 * 8;
#pragma unroll
    for (int u = 0; u < 16; u++) {
        int idx = u * 256 + t;
        int r = idx >> 8, c = idx & 255;
        sm[r][c] = src[(size_t)r * N + c];
    }
    __syncthreads();
#pragma unroll
    for (int u = 0; u < 4; u++) {
        int wv = u * 256 + t;
        int an = wv >> 5, lane = wv & 31;
        int gr = lane >> 2, gc = lane & 3;
        uint2 v;
        v.x = h2u(sm[2 * gc][an * 8 + gr],     sm[2 * gc + 1][an * 8 + gr]);
        v.y = h2u(sm[2 * gc + 8][an * 8 + gr], sm[2 * gc + 9][an * 8 + gr]);
        outp[((size_t)ak * (N >> 3) + an0 + an) * 32 + lane] = v;
    }
}

// ---------------------------------------------------------------------------
// FP16 GEMM on packed operands. 128x128 tile, BK=64 (16 iters), 256 thr,
// warp = 64Mx32N, single-sync 3-stage cp.async pipeline (3 x 32KB).
// MODE 0: row-major fp32 C + bias (proj). MODE 2: scatter packed Q/K/V.
// ---------------------------------------------------------------------------
template <int MODE>
__global__ __launch_bounds__(256, 2) void gemm_f16_kernel(
    const __half* __restrict__ Ap, const __half* __restrict__ Bp,
    const float* __restrict__ bias, float* __restrict__ C,
    __half* __restrict__ qp, __half* __restrict__ kp, __half* __restrict__ vp,
    int M, int N, int K)
{
    extern __shared__ float smf[];
    char* smb = (char*)smf;

    const int tid  = threadIdx.x;
    const int lane = tid & 31;
    const int warp = tid >> 5;
    const int bm = blockIdx.y * 128;
    const int bn = blockIdx.x * 128;
    const int wm2 = (warp & 1) * 4;        // warp m-atom base
    const int wn2 = (warp >> 1) * 4;       // warp n-atom base
    const int gr = lane >> 2;
    const int gc = lane & 3;
    const int K16 = K >> 4, N8 = N >> 3;

    auto prefetch = [&](int t, int s) {
        char* Ad = smb + s * 32768;
        char* Bd = Ad + 16384;
#pragma unroll
        for (int u = 0; u < 4; u++) {
            int c = u * 256 + tid;                    // 0..1023 x 16B
            int ai = c >> 7, aj = (c >> 5) & 3, al = c & 31;
            const char* ag = (const char*)Ap
                + (((size_t)((bm >> 4) + ai) * K16 + t * 4 + aj) * 32 + al) * 16;
            cp16(Ad + c * 16, ag);
            int atom = c >> 4, bw = c & 15;
            int aj2 = atom >> 4, an = atom & 15;
            const char* bg = (const char*)Bp
                + ((size_t)(t * 4 + aj2) * N8 + (bn >> 3) + an) * 256 + bw * 16;
            cp16(Bd + c * 16, bg);
        }
    };

    float c[4][4][4];
#pragma unroll
    for (int i = 0; i < 4; i++)
#pragma unroll
        for (int j = 0; j < 4; j++)
#pragma unroll
            for (int r = 0; r < 4; r++) c[i][j][r] = 0.0f;

    const int nit = K / 64;                // 16
    prefetch(0, 0); cp_commit();
    prefetch(1, 1); cp_commit();

    for (int t = 0; t < nit; t++) {
        if (t + 1 < nit) cp_wait<1>(); else cp_wait<0>();
        __syncthreads();
        if (t + 2 < nit) { prefetch(t + 2, (t + 2) % 3); cp_commit(); }

        const char* st = smb + (t % 3) * 32768;
        const uint4* Af = (const uint4*)st;
        const uint2* Bf = (const uint2*)(st + 16384);

#pragma unroll
        for (int ks = 0; ks < 4; ks++) {
            uint4 a4[4];
#pragma unroll
            for (int i = 0; i < 4; i++)
                a4[i] = Af[(((wm2 + i) << 2) + ks) * 32 + lane];
            uint2 b2[4];
#pragma unroll
            for (int j = 0; j < 4; j++)
                b2[j] = Bf[((ks << 4) + wn2 + j) * 32 + lane];
#pragma unroll
            for (int i = 0; i < 4; i++)
#pragma unroll
                for (int j = 0; j < 4; j++)
                    mma_f16(c[i][j], a4[i], b2[j]);
        }
    }
    // no trailing sync needed: epilogue touches only registers + global

    if (MODE == 0) {
#pragma unroll
        for (int i = 0; i < 4; i++) {
#pragma unroll
            for (int j = 0; j < 4; j++) {
                int row = bm + (wm2 + i) * 16 + gr;
                int col = bn + (wn2 + j) * 8 + 2 * gc;
                float bx = bias[col], by = bias[col + 1];
                *(float2*)(C + (size_t)row * N + col) =
                    make_float2(c[i][j][0] + bx, c[i][j][1] + by);
                *(float2*)(C + (size_t)(row + 8) * N + col) =
                    make_float2(c[i][j][2] + bx, c[i][j][3] + by);
            }
        }
    } else {
        const int sec = bn >> 10;          // whole block in one of Q/K/V
#pragma unroll
        for (int i = 0; i < 4; i++) {
#pragma unroll
            for (int j = 0; j < 4; j++) {
                int row = bm + (wm2 + i) * 16 + gr;    // row, row+8
                int col = bn + (wn2 + j) * 8 + 2 * gc; // col, col+1
                float v0 = c[i][j][0] + bias[col];
                float v1 = c[i][j][1] + bias[col + 1];
                float v2 = c[i][j][2] + bias[col];
                float v3 = c[i][j][3] + bias[col + 1];
                int tt = row & 2047, b_ = row >> 11;
                int h_ = (col & 1023) >> 6, d = col & 63;
                int bh = b_ * HH + h_;
                if (sec == 0) {
                    // Q packed-A: atom=(bh*128+tt/16)*4+(d/16)
                    int kk = d & 15;       // even
                    char* base = (char*)qp
                        + ((((size_t)bh * 128 + (tt >> 4)) * 4 + (d >> 4)) * 512)
                        + ((tt & 7) * 4 + ((kk & 7) >> 1)) * 16 + ((kk >= 8) ? 8 : 0);
                    uint2 st2;
                    st2.x = h2u(v0 * 0.125f, v1 * 0.125f);   // row gr
                    st2.y = h2u(v2 * 0.125f, v3 * 0.125f);   // row gr+8
                    *(uint2*)base = st2;
                } else if (sec == 1) {
                    // K packed-B (QK): atom=(bh*32+tt/64)*32+(d/16)*8+((tt>>3)&7)
                    int kk = d & 15;
                    size_t atom = ((size_t)bh * 32 + (tt >> 6)) * 32
                                + (d >> 4) * 8 + ((tt >> 3) & 7);
                    int off = ((tt & 7) * 4 + ((kk & 7) >> 1)) * 8 + ((kk >= 8) ? 4 : 0);
                    *(uint32_t*)((char*)kp + atom * 256 + off) = h2u(v0, v1);
                    size_t atom8 = atom + 1;                 // row+8: key-atom +1
                    *(uint32_t*)((char*)kp + atom8 * 256 + off) = h2u(v2, v3);
                } else {
                    // V packed-B (PV): n=d, k=keys — scalar half stores
                    auto wrv = [&](float v, int ttv, int dv) {
                        size_t atom = ((size_t)bh * 32 + (ttv >> 6)) * 32
                                    + ((ttv >> 4) & 3) * 8 + (dv >> 3);
                        int off = ((dv & 7) * 4 + ((ttv & 7) >> 1)) * 8
                                + (((ttv & 15) >= 8) ? 4 : 0) + (ttv & 1) * 2;
                        *(__half*)((char*)vp + atom * 256 + off) = __float2half_rn(v);
                    };
                    wrv(v0, tt, d); wrv(v1, tt, d + 1);
                    wrv(v2, tt + 8, d); wrv(v3, tt + 8, d + 1);
                }
            }
        }
    }
}

// ---------------------------------------------------------------------------
// FP16 causal flash attention on packed operands.
// 128 thr / 4 warps, 128-query tiles (2x16-row chunks/warp), key tile 64.
// SMEM: P 8x2KB = 16KB + 2x(K 8KB) + 2x(V 8KB) = 48KB. Single-sync loop.
// ---------------------------------------------------------------------------
__global__ __launch_bounds__(128, 2) void attn_f16_kernel(
    const __half* __restrict__ qp, const __half* __restrict__ kp,
    const __half* __restrict__ vp, __half* __restrict__ outp)
{
    extern __shared__ float smf[];
    char* Pp  = (char*)smf;            // 16 KB
    char* Kb0 = Pp + 16384;            // 8 KB each
    char* Kb1 = Kb0 + 8192;
    char* Vb0 = Kb1 + 8192;
    char* Vb1 = Vb0 + 8192;

    const int tid  = threadIdx.x;
    const int lane = tid & 31;
    const int w    = tid >> 5;
    const int gr   = lane >> 2;
    const int gc   = lane & 3;
    const int qt = gridDim.x - 1 - blockIdx.x;   // heavy blocks first
    const int h  = blockIdx.y;
    const int b  = blockIdx.z;
    const int bh = b * HH + h;
    const int qbase_g = qt * 128;

    const char* kbase = (const char*)kp + (size_t)bh * 32 * 8192;
    const char* vbase = (const char*)vp + (size_t)bh * 32 * 8192;

    auto prefetch = [&](int kt, int pb) {
        char* Kd = pb ? Kb1 : Kb0;
        char* Vd = pb ? Vb1 : Vb0;
        const char* ks_ = kbase + (size_t)kt * 8192;
        const char* vs_ = vbase + (size_t)kt * 8192;
#pragma unroll
        for (int u = 0; u < 4; u++) {
            int c = u * 128 + tid;                // 0..511 x 16B
            cp16(Kd + c * 16, ks_ + c * 16);
            cp16(Vd + c * 16, vs_ + c * 16);
        }
    };

    prefetch(0, 0); cp_commit();

    // ---- Q fragments: direct LDG.128 from packed Q ----
    uint4 qf[2][4];
#pragma unroll
    for (int mi = 0; mi < 2; mi++) {
        const uint4* qg = (const uint4*)qp
            + ((size_t)bh * 128 + qt * 8 + w * 2 + mi) * 4 * 32 + lane;
#pragma unroll
        for (int ks = 0; ks < 4; ks++)
            qf[mi][ks] = qg[ks * 32];
    }

    float o[2][8][4];
#pragma unroll
    for (int mi = 0; mi < 2; mi++)
#pragma unroll
        for (int j = 0; j < 8; j++)
#pragma unroll
            for (int r = 0; r < 4; r++) o[mi][j][r] = 0.0f;
    float mS[2][2] = {{-1e30f, -1e30f}, {-1e30f, -1e30f}};
    float lS[2][2] = {{0.0f, 0.0f}, {0.0f, 0.0f}};

    const int ntiles = 2 * qt + 2;
    for (int kt = 0; kt < ntiles; kt++) {
        cp_wait<0>();
        __syncthreads();
        if (kt + 1 < ntiles) { prefetch(kt + 1, (kt + 1) & 1); cp_commit(); }
        const uint2* Kf = (const uint2*)((kt & 1) ? Kb1 : Kb0);
        const uint2* Vf = (const uint2*)((kt & 1) ? Vb1 : Vb0);

#pragma unroll
        for (int mi = 0; mi < 2; mi++) {
            const int wbase_g = qbase_g + w * 32 + mi * 16;
            if (kt * 64 > wbase_g) continue;   // chunk fully masked

            // ---- S = Q @ K^T ----
            float s[8][4];
#pragma unroll
            for (int j = 0; j < 8; j++) {
                s[j][0] = s[j][1] = s[j][2] = s[j][3] = 0.0f;
#pragma unroll
                for (int ks = 0; ks < 4; ks++)
                    mma_f16(s[j], qf[mi][ks], Kf[(ks * 8 + j) * 32 + lane]);
            }

            // ---- causal mask (boundary tiles only) ----
            if (kt * 64 + 63 > wbase_g) {
                const int row0 = wbase_g + gr;
                const int row1 = row0 + 8;
#pragma unroll
                for (int j = 0; j < 8; j++) {
                    int key0 = kt * 64 + j * 8 + 2 * gc;
                    if (key0     > row0) s[j][0] = -1e30f;
                    if (key0 + 1 > row0) s[j][1] = -1e30f;
                    if (key0     > row1) s[j][2] = -1e30f;
                    if (key0 + 1 > row1) s[j][3] = -1e30f;
                }
            }

            // ---- online softmax ----
            float mx0 = -1e30f, mx1 = -1e30f;
#pragma unroll
            for (int j = 0; j < 8; j++) {
                mx0 = fmaxf(mx0, fmaxf(s[j][0], s[j][1]));
                mx1 = fmaxf(mx1, fmaxf(s[j][2], s[j][3]));
            }
            mx0 = fmaxf(mx0, __shfl_xor_sync(0xffffffffu, mx0, 1));
            mx0 = fmaxf(mx0, __shfl_xor_sync(0xffffffffu, mx0, 2));
            mx1 = fmaxf(mx1, __shfl_xor_sync(0xffffffffu, mx1, 1));
            mx1 = fmaxf(mx1, __shfl_xor_sync(0xffffffffu, mx1, 2));

            float mn0 = fmaxf(mS[mi][0], mx0), mn1 = fmaxf(mS[mi][1], mx1);
            float cr0 = __expf(mS[mi][0] - mn0), cr1 = __expf(mS[mi][1] - mn1);
            lS[mi][0] *= cr0; lS[mi][1] *= cr1;
#pragma unroll
            for (int j = 0; j < 8; j++) {
                o[mi][j][0] *= cr0; o[mi][j][1] *= cr0;
                o[mi][j][2] *= cr1; o[mi][j][3] *= cr1;
            }

            // ---- exp + packed-P write (1x STS.64 per key atom) ----
            float rs0 = 0.0f, rs1 = 0.0f;
            char* pbase = Pp + (w * 2 + mi) * 2048;
            const int loff = (gr * 4 + gc) * 16;
#pragma unroll
            for (int j = 0; j < 8; j++) {
                float p0 = __expf(s[j][0] - mn0);
                float p1 = __expf(s[j][1] - mn0);
                float p2 = __expf(s[j][2] - mn1);
                float p3 = __expf(s[j][3] - mn1);
                rs0 += p0 + p1; rs1 += p2 + p3;
                uint2 st2;
                st2.x = h2u(p0, p1);    // row gr
                st2.y = h2u(p2, p3);    // row gr+8
                *(uint2*)(pbase + (j >> 1) * 512 + loff + (j & 1) * 8) = st2;
            }
            rs0 += __shfl_xor_sync(0xffffffffu, rs0, 1);
            rs0 += __shfl_xor_sync(0xffffffffu, rs0, 2);
            rs1 += __shfl_xor_sync(0xffffffffu, rs1, 1);
            rs1 += __shfl_xor_sync(0xffffffffu, rs1, 2);
            lS[mi][0] += rs0; lS[mi][1] += rs1;
            mS[mi][0] = mn0; mS[mi][1] = mn1;
            __syncwarp();   // P atoms are warp-private

            // ---- P fragments: LDS.128 per k-atom ----
            uint4 pf[4];
#pragma unroll
            for (int kc = 0; kc < 4; kc++)
                pf[kc] = *(const uint4*)(pbase + kc * 512 + lane * 16);

            // ---- O += P @ V ----
#pragma unroll
            for (int jd = 0; jd < 8; jd++)
#pragma unroll
                for (int kc = 0; kc < 4; kc++)
                    mma_f16(o[mi][jd], pf[kc], Vf[(kc * 8 + jd) * 32 + lane]);
        }
    }

    // ---- epilogue: normalize + write packed-A fp16 for proj ----
#pragma unroll
    for (int mi = 0; mi < 2; mi++) {
        float iv0 = 1.0f / lS[mi][0], iv1 = 1.0f / lS[mi][1];
        int rowg = b * TT + qbase_g + w * 32 + mi * 16;   // 16-aligned
        size_t ratom = (size_t)(rowg >> 4);
#pragma unroll
        for (int jd = 0; jd < 8; jd++) {
            size_t katom = h * 4 + (jd >> 1);
            char* base = (char*)outp + (ratom * 64 + katom) * 512
                       + (gr * 4 + gc) * 16 + (jd & 1) * 8;
            uint2 st2;
            st2.x = h2u(o[mi][jd][0] * iv0, o[mi][jd][1] * iv0);
            st2.y = h2u(o[mi][jd][2] * iv1, o[mi][jd][3] * iv1);
            *(uint2*)base = st2;
        }
    }
}

// ---------------------------------------------------------------------------
// Launch
// ---------------------------------------------------------------------------
extern "C" void kernel_launch(void* const* d_in, const int* in_sizes, int n_in,
                              void* d_out, int out_size)
{
    const float* x      = (const float*)d_in[0];
    const float* qkv_w  = (const float*)d_in[1];
    const float* qkv_b  = (const float*)d_in[2];
    const float* proj_w = (const float*)d_in[3];
    const float* proj_b = (const float*)d_in[4];
    float* out = (float*)d_out;

    __half *qp, *kpp, *vpp, *att_s, *xt, *wqkv, *wproj;
    cudaGetSymbolAddress((void**)&qp,    g_qp);
    cudaGetSymbolAddress((void**)&kpp,   g_kp);
    cudaGetSymbolAddress((void**)&vpp,   g_vp);
    cudaGetSymbolAddress((void**)&att_s, g_att);
    cudaGetSymbolAddress((void**)&xt,    g_xt);
    cudaGetSymbolAddress((void**)&wqkv,  g_wqkv);
    cudaGetSymbolAddress((void**)&wproj, g_wproj);

    const int GEMM_SMEM = 3 * 32768;     // 98304
    const int ATTN_SMEM = 48 * 1024;     // 49152
    cudaFuncSetAttribute(gemm_f16_kernel<2>,
                         cudaFuncAttributeMaxDynamicSharedMemorySize, GEMM_SMEM);
    cudaFuncSetAttribute(gemm_f16_kernel<0>,
                         cudaFuncAttributeMaxDynamicSharedMemorySize, GEMM_SMEM);
    cudaFuncSetAttribute(attn_f16_kernel,
                         cudaFuncAttributeMaxDynamicSharedMemorySize, ATTN_SMEM);

    // 0) Prepass: pack+convert x (A-atoms) and both weights (B-atoms)
    pack_a16_kernel<<<dim3(DD / 128, MROWS / 16), 256>>>(x, (uint4*)xt, MROWS, DD);
    pack_b16_kernel<<<dim3(QKV_N / 256, DD / 16), 256>>>(qkv_w, (uint2*)wqkv, DD, QKV_N);
    pack_b16_kernel<<<dim3(DD / 256, DD / 16), 256>>>(proj_w, (uint2*)wproj, DD, DD);

    // 1) QKV GEMM -> packed Q / K / V directly
    dim3 g1(QKV_N / 128, MROWS / 128);
    gemm_f16_kernel<2><<<g1, 256, GEMM_SMEM>>>(xt, wqkv, qkv_b, nullptr,
                                               qp, kpp, vpp, MROWS, QKV_N, DD);

    // 2) Causal multi-head attention on packed fp16 operands
    dim3 ga(TT / 128, HH, BB);
    attn_f16_kernel<<<ga, 128, ATTN_SMEM>>>(qp, kpp, vpp, att_s);

    // 3) Output projection (packed in, row-major fp32 out)
    dim3 g2(DD / 128, MROWS / 128);
    gemm_f16_kernel<0><<<g2, 256, GEMM_SMEM>>>(att_s, wproj, proj_b, out,
                                               nullptr, nullptr, nullptr,
                                               MROWS, DD, DD);
}

// round 11
// speedup vs baseline: 2.5678x; 1.0907x over previous
#include <cuda_runtime.h>
#include <cuda_fp16.h>
#include <cstdint>

// Problem constants
#define BB 4
#define TT 2048
#define DD 1024
#define HH 16
#define HDIM 64
#define MROWS (BB * TT)            // 8192
#define QKV_N (3 * DD)             // 3072

// Scratch (allocation-free rule: __device__ globals) — all fp16 packed
__device__ __half g_qp[(size_t)MROWS * DD];      // 16 MB packed-A Q (x0.125)
__device__ __half g_kp[(size_t)MROWS * DD];      // 16 MB packed-B K (QK layout)
__device__ __half g_vp[(size_t)MROWS * DD];      // 16 MB packed-B V (PV layout)
__device__ __half g_att[(size_t)MROWS * DD];     // 16 MB packed-A attention out
__device__ __half g_xt[(size_t)MROWS * DD];      // 16 MB packed-A x
__device__ __half g_wqkv[(size_t)DD * QKV_N];    //  6 MB packed-B qkv_w
__device__ __half g_wproj[(size_t)DD * DD];      //  2 MB packed-B proj_w

__device__ __forceinline__ uint32_t h2u(float a, float b) {
    __half2 h = __floats2half2_rn(a, b);
    return *reinterpret_cast<uint32_t*>(&h);
}

__device__ __forceinline__ void mma_f16(float c[4], uint4 a, uint2 b) {
    asm volatile(
        "mma.sync.aligned.m16n8k16.row.col.f32.f16.f16.f32 "
        "{%0,%1,%2,%3}, {%4,%5,%6,%7}, {%8,%9}, {%0,%1,%2,%3};"
        : "+f"(c[0]), "+f"(c[1]), "+f"(c[2]), "+f"(c[3])
        : "r"(a.x), "r"(a.y), "r"(a.z), "r"(a.w), "r"(b.x), "r"(b.y));
}

__device__ __forceinline__ void cp16(void* dst, const void* src) {
    uint32_t d = (uint32_t)__cvta_generic_to_shared(dst);
    asm volatile("cp.async.cg.shared.global [%0], [%1], 16;" :: "r"(d), "l"(src));
}
__device__ __forceinline__ void cp_commit() {
    asm volatile("cp.async.commit_group;");
}
template <int N> __device__ __forceinline__ void cp_wait() {
    asm volatile("cp.async.wait_group %0;" :: "n"(N));
}

// ---------------------------------------------------------------------------
// Prepass: pack A [M][K] fp32 row-major -> fp16 A-atoms (16r x 16k, 512B).
// ---------------------------------------------------------------------------
__global__ __launch_bounds__(256) void pack_a16_kernel(
    const float* __restrict__ in, uint4* __restrict__ outp, int M, int K)
{
    __shared__ float sm[16][132];
    const int t = threadIdx.x;
    const int am  = blockIdx.y;
    const int ak0 = blockIdx.x * 8;
    const float* src = in + (size_t)am * 16 * K + ak0 * 16;
#pragma unroll
    for (int u = 0; u < 8; u++) {
        int idx = u * 256 + t;
        int r = idx >> 7, c = idx & 127;
        sm[r][c] = src[(size_t)r * K + c];
    }
    __syncthreads();
    const int j = t >> 5, lane = t & 31;
    const int gr = lane >> 2, gc = lane & 3;
    const int k0 = j * 16;
    uint4 v;
    v.x = h2u(sm[gr][k0 + 2 * gc],     sm[gr][k0 + 2 * gc + 1]);
    v.y = h2u(sm[gr + 8][k0 + 2 * gc], sm[gr + 8][k0 + 2 * gc + 1]);
    v.z = h2u(sm[gr][k0 + 2 * gc + 8], sm[gr][k0 + 2 * gc + 9]);
    v.w = h2u(sm[gr + 8][k0 + 2 * gc + 8], sm[gr + 8][k0 + 2 * gc + 9]);
    outp[((size_t)am * (K >> 4) + ak0 + j) * 32 + lane] = v;
}

// ---------------------------------------------------------------------------
// Prepass: pack B [K][N] fp32 row-major -> fp16 B-atoms (16k x 8n, 256B).
// ---------------------------------------------------------------------------
__global__ __launch_bounds__(256) void pack_b16_kernel(
    const float* __restrict__ in, uint2* __restrict__ outp, int K, int N)
{
    __shared__ float sm[16][260];
    const int t = threadIdx.x;
    const int ak  = blockIdx.y;
    const int an0 = blockIdx.x * 32;
    const float* src = in + (size_t)ak * 16 * N + an0 * 8;
#pragma unroll
    for (int u = 0; u < 16; u++) {
        int idx = u * 256 + t;
        int r = idx >> 8, c = idx & 255;
        sm[r][c] = src[(size_t)r * N + c];
    }
    __syncthreads();
#pragma unroll
    for (int u = 0; u < 4; u++) {
        int wv = u * 256 + t;
        int an = wv >> 5, lane = wv & 31;
        int gr = lane >> 2, gc = lane & 3;
        uint2 v;
        v.x = h2u(sm[2 * gc][an * 8 + gr],     sm[2 * gc + 1][an * 8 + gr]);
        v.y = h2u(sm[2 * gc + 8][an * 8 + gr], sm[2 * gc + 9][an * 8 + gr]);
        outp[((size_t)ak * (N >> 3) + an0 + an) * 32 + lane] = v;
    }
}

// ---------------------------------------------------------------------------
// FP16 GEMM on packed operands (unchanged from R10).
// MODE 0: row-major fp32 C + bias (proj). MODE 2: scatter packed Q/K/V.
// ---------------------------------------------------------------------------
template <int MODE>
__global__ __launch_bounds__(256, 2) void gemm_f16_kernel(
    const __half* __restrict__ Ap, const __half* __restrict__ Bp,
    const float* __restrict__ bias, float* __restrict__ C,
    __half* __restrict__ qp, __half* __restrict__ kp, __half* __restrict__ vp,
    int M, int N, int K)
{
    extern __shared__ float smf[];
    char* smb = (char*)smf;

    const int tid  = threadIdx.x;
    const int lane = tid & 31;
    const int warp = tid >> 5;
    const int bm = blockIdx.y * 128;
    const int bn = blockIdx.x * 128;
    const int wm2 = (warp & 1) * 4;
    const int wn2 = (warp >> 1) * 4;
    const int gr = lane >> 2;
    const int gc = lane & 3;
    const int K16 = K >> 4, N8 = N >> 3;

    auto prefetch = [&](int t, int s) {
        char* Ad = smb + s * 32768;
        char* Bd = Ad + 16384;
#pragma unroll
        for (int u = 0; u < 4; u++) {
            int c = u * 256 + tid;
            int ai = c >> 7, aj = (c >> 5) & 3, al = c & 31;
            const char* ag = (const char*)Ap
                + (((size_t)((bm >> 4) + ai) * K16 + t * 4 + aj) * 32 + al) * 16;
            cp16(Ad + c * 16, ag);
            int atom = c >> 4, bw = c & 15;
            int aj2 = atom >> 4, an = atom & 15;
            const char* bg = (const char*)Bp
                + ((size_t)(t * 4 + aj2) * N8 + (bn >> 3) + an) * 256 + bw * 16;
            cp16(Bd + c * 16, bg);
        }
    };

    float c[4][4][4];
#pragma unroll
    for (int i = 0; i < 4; i++)
#pragma unroll
        for (int j = 0; j < 4; j++)
#pragma unroll
            for (int r = 0; r < 4; r++) c[i][j][r] = 0.0f;

    const int nit = K / 64;
    prefetch(0, 0); cp_commit();
    prefetch(1, 1); cp_commit();

    for (int t = 0; t < nit; t++) {
        if (t + 1 < nit) cp_wait<1>(); else cp_wait<0>();
        __syncthreads();
        if (t + 2 < nit) { prefetch(t + 2, (t + 2) % 3); cp_commit(); }

        const char* st = smb + (t % 3) * 32768;
        const uint4* Af = (const uint4*)st;
        const uint2* Bf = (const uint2*)(st + 16384);

#pragma unroll
        for (int ks = 0; ks < 4; ks++) {
            uint4 a4[4];
#pragma unroll
            for (int i = 0; i < 4; i++)
                a4[i] = Af[(((wm2 + i) << 2) + ks) * 32 + lane];
            uint2 b2[4];
#pragma unroll
            for (int j = 0; j < 4; j++)
                b2[j] = Bf[((ks << 4) + wn2 + j) * 32 + lane];
#pragma unroll
            for (int i = 0; i < 4; i++)
#pragma unroll
                for (int j = 0; j < 4; j++)
                    mma_f16(c[i][j], a4[i], b2[j]);
        }
    }

    if (MODE == 0) {
#pragma unroll
        for (int i = 0; i < 4; i++) {
#pragma unroll
            for (int j = 0; j < 4; j++) {
                int row = bm + (wm2 + i) * 16 + gr;
                int col = bn + (wn2 + j) * 8 + 2 * gc;
                float bx = bias[col], by = bias[col + 1];
                *(float2*)(C + (size_t)row * N + col) =
                    make_float2(c[i][j][0] + bx, c[i][j][1] + by);
                *(float2*)(C + (size_t)(row + 8) * N + col) =
                    make_float2(c[i][j][2] + bx, c[i][j][3] + by);
            }
        }
    } else {
        const int sec = bn >> 10;
#pragma unroll
        for (int i = 0; i < 4; i++) {
#pragma unroll
            for (int j = 0; j < 4; j++) {
                int row = bm + (wm2 + i) * 16 + gr;
                int col = bn + (wn2 + j) * 8 + 2 * gc;
                float v0 = c[i][j][0] + bias[col];
                float v1 = c[i][j][1] + bias[col + 1];
                float v2 = c[i][j][2] + bias[col];
                float v3 = c[i][j][3] + bias[col + 1];
                int tt = row & 2047, b_ = row >> 11;
                int h_ = (col & 1023) >> 6, d = col & 63;
                int bh = b_ * HH + h_;
                if (sec == 0) {
                    int kk = d & 15;
                    char* base = (char*)qp
                        + ((((size_t)bh * 128 + (tt >> 4)) * 4 + (d >> 4)) * 512)
                        + ((tt & 7) * 4 + ((kk & 7) >> 1)) * 16 + ((kk >= 8) ? 8 : 0);
                    uint2 st2;
                    st2.x = h2u(v0 * 0.125f, v1 * 0.125f);
                    st2.y = h2u(v2 * 0.125f, v3 * 0.125f);
                    *(uint2*)base = st2;
                } else if (sec == 1) {
                    int kk = d & 15;
                    size_t atom = ((size_t)bh * 32 + (tt >> 6)) * 32
                                + (d >> 4) * 8 + ((tt >> 3) & 7);
                    int off = ((tt & 7) * 4 + ((kk & 7) >> 1)) * 8 + ((kk >= 8) ? 4 : 0);
                    *(uint32_t*)((char*)kp + atom * 256 + off) = h2u(v0, v1);
                    size_t atom8 = atom + 1;
                    *(uint32_t*)((char*)kp + atom8 * 256 + off) = h2u(v2, v3);
                } else {
                    auto wrv = [&](float v, int ttv, int dv) {
                        size_t atom = ((size_t)bh * 32 + (ttv >> 6)) * 32
                                    + ((ttv >> 4) & 3) * 8 + (dv >> 3);
                        int off = ((dv & 7) * 4 + ((ttv & 7) >> 1)) * 8
                                + (((ttv & 15) >= 8) ? 4 : 0) + (ttv & 1) * 2;
                        *(__half*)((char*)vp + atom * 256 + off) = __float2half_rn(v);
                    };
                    wrv(v0, tt, d); wrv(v1, tt, d + 1);
                    wrv(v2, tt + 8, d); wrv(v3, tt + 8, d + 1);
                }
            }
        }
    }
}

// ---------------------------------------------------------------------------
// FP16 causal flash attention, 64-query tiles (1x16-row chunk per warp).
// 128 thr / 4 warps, key tile 64; higher occupancy (3 blocks/SM) to hide
// the softmax serial chain. SMEM: P 8KB + 2x(K 8KB) + 2x(V 8KB) = 40KB.
// ---------------------------------------------------------------------------
__global__ __launch_bounds__(128, 3) void attn_f16_kernel(
    const __half* __restrict__ qp, const __half* __restrict__ kp,
    const __half* __restrict__ vp, __half* __restrict__ outp)
{
    extern __shared__ float smf[];
    char* Pp  = (char*)smf;            // 8 KB (4 warps x 2KB)
    char* Kb0 = Pp + 8192;             // 8 KB each
    char* Kb1 = Kb0 + 8192;
    char* Vb0 = Kb1 + 8192;
    char* Vb1 = Vb0 + 8192;

    const int tid  = threadIdx.x;
    const int lane = tid & 31;
    const int w    = tid >> 5;
    const int gr   = lane >> 2;
    const int gc   = lane & 3;
    const int qt = gridDim.x - 1 - blockIdx.x;   // heavy blocks first
    const int h  = blockIdx.y;
    const int b  = blockIdx.z;
    const int bh = b * HH + h;
    const int qbase_g = qt * 64;

    const char* kbase = (const char*)kp + (size_t)bh * 32 * 8192;
    const char* vbase = (const char*)vp + (size_t)bh * 32 * 8192;

    auto prefetch = [&](int kt, int pb) {
        char* Kd = pb ? Kb1 : Kb0;
        char* Vd = pb ? Vb1 : Vb0;
        const char* ks_ = kbase + (size_t)kt * 8192;
        const char* vs_ = vbase + (size_t)kt * 8192;
#pragma unroll
        for (int u = 0; u < 4; u++) {
            int c = u * 128 + tid;                // 0..511 x 16B
            cp16(Kd + c * 16, ks_ + c * 16);
            cp16(Vd + c * 16, vs_ + c * 16);
        }
    };

    prefetch(0, 0); cp_commit();

    // ---- Q fragments: direct LDG.128 from packed Q (warp = 16 rows) ----
    uint4 qf[4];
    {
        const uint4* qg = (const uint4*)qp
            + ((size_t)bh * 128 + qt * 4 + w) * 4 * 32 + lane;
#pragma unroll
        for (int ks = 0; ks < 4; ks++)
            qf[ks] = qg[ks * 32];
    }

    float o[8][4];
#pragma unroll
    for (int j = 0; j < 8; j++)
#pragma unroll
        for (int r = 0; r < 4; r++) o[j][r] = 0.0f;
    float m0 = -1e30f, m1 = -1e30f, l0 = 0.0f, l1 = 0.0f;

    const int wbase_g = qbase_g + w * 16;
    const int ntiles = qt + 1;
    for (int kt = 0; kt < ntiles; kt++) {
        cp_wait<0>();
        __syncthreads();
        if (kt + 1 < ntiles) { prefetch(kt + 1, (kt + 1) & 1); cp_commit(); }
        const uint2* Kf = (const uint2*)((kt & 1) ? Kb1 : Kb0);
        const uint2* Vf = (const uint2*)((kt & 1) ? Vb1 : Vb0);

        // ---- S = Q @ K^T ----
        float s[8][4];
#pragma unroll
        for (int j = 0; j < 8; j++) {
            s[j][0] = s[j][1] = s[j][2] = s[j][3] = 0.0f;
#pragma unroll
            for (int ks = 0; ks < 4; ks++)
                mma_f16(s[j], qf[ks], Kf[(ks * 8 + j) * 32 + lane]);
        }

        // ---- causal mask (boundary tile only) ----
        if (kt * 64 + 63 > wbase_g) {
            const int row0 = wbase_g + gr;
            const int row1 = row0 + 8;
#pragma unroll
            for (int j = 0; j < 8; j++) {
                int key0 = kt * 64 + j * 8 + 2 * gc;
                if (key0     > row0) s[j][0] = -1e30f;
                if (key0 + 1 > row0) s[j][1] = -1e30f;
                if (key0     > row1) s[j][2] = -1e30f;
                if (key0 + 1 > row1) s[j][3] = -1e30f;
            }
        }

        // ---- online softmax ----
        float mx0 = -1e30f, mx1 = -1e30f;
#pragma unroll
        for (int j = 0; j < 8; j++) {
            mx0 = fmaxf(mx0, fmaxf(s[j][0], s[j][1]));
            mx1 = fmaxf(mx1, fmaxf(s[j][2], s[j][3]));
        }
        mx0 = fmaxf(mx0, __shfl_xor_sync(0xffffffffu, mx0, 1));
        mx0 = fmaxf(mx0, __shfl_xor_sync(0xffffffffu, mx0, 2));
        mx1 = fmaxf(mx1, __shfl_xor_sync(0xffffffffu, mx1, 1));
        mx1 = fmaxf(mx1, __shfl_xor_sync(0xffffffffu, mx1, 2));

        float mn0 = fmaxf(m0, mx0), mn1 = fmaxf(m1, mx1);
        float cr0 = __expf(m0 - mn0), cr1 = __expf(m1 - mn1);
        l0 *= cr0; l1 *= cr1;
#pragma unroll
        for (int j = 0; j < 8; j++) {
            o[j][0] *= cr0; o[j][1] *= cr0;
            o[j][2] *= cr1; o[j][3] *= cr1;
        }

        // ---- exp + packed-P write ----
        float rs0 = 0.0f, rs1 = 0.0f;
        char* pbase = Pp + w * 2048;
        const int loff = (gr * 4 + gc) * 16;
#pragma unroll
        for (int j = 0; j < 8; j++) {
            float p0 = __expf(s[j][0] - mn0);
            float p1 = __expf(s[j][1] - mn0);
            float p2 = __expf(s[j][2] - mn1);
            float p3 = __expf(s[j][3] - mn1);
            rs0 += p0 + p1; rs1 += p2 + p3;
            uint2 st2;
            st2.x = h2u(p0, p1);
            st2.y = h2u(p2, p3);
            *(uint2*)(pbase + (j >> 1) * 512 + loff + (j & 1) * 8) = st2;
        }
        rs0 += __shfl_xor_sync(0xffffffffu, rs0, 1);
        rs0 += __shfl_xor_sync(0xffffffffu, rs0, 2);
        rs1 += __shfl_xor_sync(0xffffffffu, rs1, 1);
        rs1 += __shfl_xor_sync(0xffffffffu, rs1, 2);
        l0 += rs0; l1 += rs1;
        m0 = mn0; m1 = mn1;
        __syncwarp();   // P atoms warp-private

        // ---- P fragments + O += P @ V ----
        uint4 pf[4];
#pragma unroll
        for (int kc = 0; kc < 4; kc++)
            pf[kc] = *(const uint4*)(pbase + kc * 512 + lane * 16);
#pragma unroll
        for (int jd = 0; jd < 8; jd++)
#pragma unroll
            for (int kc = 0; kc < 4; kc++)
                mma_f16(o[jd], pf[kc], Vf[(kc * 8 + jd) * 32 + lane]);
    }

    // ---- epilogue: normalize + write packed-A fp16 for proj ----
    float iv0 = 1.0f / l0, iv1 = 1.0f / l1;
    int rowg = b * TT + wbase_g;                 // 16-aligned
    size_t ratom = (size_t)(rowg >> 4);
#pragma unroll
    for (int jd = 0; jd < 8; jd++) {
        size_t katom = h * 4 + (jd >> 1);
        char* base = (char*)outp + (ratom * 64 + katom) * 512
                   + (gr * 4 + gc) * 16 + (jd & 1) * 8;
        uint2 st2;
        st2.x = h2u(o[jd][0] * iv0, o[jd][1] * iv0);
        st2.y = h2u(o[jd][2] * iv1, o[jd][3] * iv1);
        *(uint2*)base = st2;
    }
}

// ---------------------------------------------------------------------------
// Launch
// ---------------------------------------------------------------------------
extern "C" void kernel_launch(void* const* d_in, const int* in_sizes, int n_in,
                              void* d_out, int out_size)
{
    const float* x      = (const float*)d_in[0];
    const float* qkv_w  = (const float*)d_in[1];
    const float* qkv_b  = (const float*)d_in[2];
    const float* proj_w = (const float*)d_in[3];
    const float* proj_b = (const float*)d_in[4];
    float* out = (float*)d_out;

    __half *qp, *kpp, *vpp, *att_s, *xt, *wqkv, *wproj;
    cudaGetSymbolAddress((void**)&qp,    g_qp);
    cudaGetSymbolAddress((void**)&kpp,   g_kp);
    cudaGetSymbolAddress((void**)&vpp,   g_vp);
    cudaGetSymbolAddress((void**)&att_s, g_att);
    cudaGetSymbolAddress((void**)&xt,    g_xt);
    cudaGetSymbolAddress((void**)&wqkv,  g_wqkv);
    cudaGetSymbolAddress((void**)&wproj, g_wproj);

    const int GEMM_SMEM = 3 * 32768;     // 98304
    const int ATTN_SMEM = 40 * 1024;     // 40960
    cudaFuncSetAttribute(gemm_f16_kernel<2>,
                         cudaFuncAttributeMaxDynamicSharedMemorySize, GEMM_SMEM);
    cudaFuncSetAttribute(gemm_f16_kernel<0>,
                         cudaFuncAttributeMaxDynamicSharedMemorySize, GEMM_SMEM);
    cudaFuncSetAttribute(attn_f16_kernel,
                         cudaFuncAttributeMaxDynamicSharedMemorySize, ATTN_SMEM);

    // 0) Prepass: pack+convert x (A-atoms) and both weights (B-atoms)
    pack_a16_kernel<<<dim3(DD / 128, MROWS / 16), 256>>>(x, (uint4*)xt, MROWS, DD);
    pack_b16_kernel<<<dim3(QKV_N / 256, DD / 16), 256>>>(qkv_w, (uint2*)wqkv, DD, QKV_N);
    pack_b16_kernel<<<dim3(DD / 256, DD / 16), 256>>>(proj_w, (uint2*)wproj, DD, DD);

    // 1) QKV GEMM -> packed Q / K / V directly
    dim3 g1(QKV_N / 128, MROWS / 128);
    gemm_f16_kernel<2><<<g1, 256, GEMM_SMEM>>>(xt, wqkv, qkv_b, nullptr,
                                               qp, kpp, vpp, MROWS, QKV_N, DD);

    // 2) Causal multi-head attention (64-query tiles, occ 3)
    dim3 ga(TT / 64, HH, BB);
    attn_f16_kernel<<<ga, 128, ATTN_SMEM>>>(qp, kpp, vpp, att_s);

    // 3) Output projection (packed in, row-major fp32 out)
    dim3 g2(DD / 128, MROWS / 128);
    gemm_f16_kernel<0><<<g2, 256, GEMM_SMEM>>>(att_s, wproj, proj_b, out,
                                               nullptr, nullptr, nullptr,
                                               MROWS, DD, DD);
}